// round 5
// baseline (speedup 1.0000x reference)
#include <cuda_runtime.h>
#include <cstdint>

#define T_DIM 256
#define B_DIM 128
#define N_DIM 4
#define L_WIN 64
#define WARPS_PB 10
#define THREADS (WARPS_PB * 32)
#define NWARPS_TOTAL (T_DIM * B_DIM / 32 * 32) // 32768 sequences, 1 warp each

typedef unsigned long long ull;

// ---------- f32x2 packed helpers (sm_100+) ----------
__device__ __forceinline__ ull pack2(float lo, float hi) {
    ull r;
    asm("mov.b64 %0, {%1, %2};" : "=l"(r) : "f"(lo), "f"(hi));
    return r;
}
__device__ __forceinline__ void unpack2(ull v, float& lo, float& hi) {
    asm("mov.b64 {%0, %1}, %2;" : "=f"(lo), "=f"(hi) : "l"(v));
}
__device__ __forceinline__ ull fma2(ull a, ull b, ull c) {
    ull d;
    asm("fma.rn.f32x2 %0, %1, %2, %3;" : "=l"(d) : "l"(a), "l"(b), "l"(c));
    return d;
}
__device__ __forceinline__ ull add2(ull a, ull b) {
    ull d;
    asm("add.rn.f32x2 %0, %1, %2;" : "=l"(d) : "l"(a), "l"(b));
    return d;
}

// ---------- fast activations (MUFU EX2 + RCP) ----------
__device__ __forceinline__ float sigf(float x) {
    float e = __expf(-x);
    return __fdividef(1.0f, 1.0f + e);
}
__device__ __forceinline__ float tanh_fast(float x) {
    float e = __expf(2.0f * x);
    return 1.0f - __fdividef(2.0f, e + 1.0f);
}

// One warp per (t, b) sequence. Lane u owns hidden unit u of the H=32 "his"
// LSTM. h is broadcast via shared memory (duplicated-pair layout so LDS.128
// feeds fma.rn.f32x2 with no re-packing). Int LSTM (H=8): lane l computes
// gate row l; units live in lanes 0..7.
__global__ void __launch_bounds__(THREADS, 1) traj_kernel(
    const float* __restrict__ inputs,
    const float* __restrict__ Wih_his, const float* __restrict__ Whh_his,
    const float* __restrict__ bih_his, const float* __restrict__ bhh_his,
    const float* __restrict__ Wih_int, const float* __restrict__ Whh_int,
    const float* __restrict__ bih_int, const float* __restrict__ bhh_int,
    const float* __restrict__ W_out, const float* __restrict__ b_out,
    float* __restrict__ out)
{
    // per-warp, ping-pong broadcast buffers
    __shared__ ulonglong2 hb[2][WARPS_PB][16]; // 32 duplicated (h,h) pairs
    __shared__ float      ib[2][WARPS_PB][8];  // 8 int hidden values

    const unsigned FULL = 0xffffffffu;
    const int lane = threadIdx.x & 31;
    const int w = threadIdx.x >> 5;
    const int gw = blockIdx.x * WARPS_PB + w;
    if (gw >= NWARPS_TOTAL) return;

    const int t = (T_DIM - 1) - (gw >> 7);   // long windows first
    const int b = gw & (B_DIM - 1);

    // ---- per-lane register weights ----
    // Whh_his: [128, 32] row-major; gate-g row for unit u is 32*g + u.
    ull w_if[32], w_go[32];
#pragma unroll
    for (int k = 0; k < 32; k++) {
        w_if[k] = pack2(Whh_his[(lane)      * 32 + k], Whh_his[(32 + lane) * 32 + k]);
        w_go[k] = pack2(Whh_his[(64 + lane) * 32 + k], Whh_his[(96 + lane) * 32 + k]);
    }
    ull wx0_if = pack2(Wih_his[(lane) * 2 + 0],      Wih_his[(32 + lane) * 2 + 0]);
    ull wx1_if = pack2(Wih_his[(lane) * 2 + 1],      Wih_his[(32 + lane) * 2 + 1]);
    ull wx0_go = pack2(Wih_his[(64 + lane) * 2 + 0], Wih_his[(96 + lane) * 2 + 0]);
    ull wx1_go = pack2(Wih_his[(64 + lane) * 2 + 1], Wih_his[(96 + lane) * 2 + 1]);
    ull bb_if = pack2(bih_his[lane] + bhh_his[lane],
                      bih_his[32 + lane] + bhh_his[32 + lane]);
    ull bb_go = pack2(bih_his[64 + lane] + bhh_his[64 + lane],
                      bih_his[96 + lane] + bhh_his[96 + lane]);

    float wi0 = Whh_int[lane * 8 + 0], wi1 = Whh_int[lane * 8 + 1];
    float wi2 = Whh_int[lane * 8 + 2], wi3 = Whh_int[lane * 8 + 3];
    float wi4 = Whh_int[lane * 8 + 4], wi5 = Whh_int[lane * 8 + 5];
    float wi6 = Whh_int[lane * 8 + 6], wi7 = Whh_int[lane * 8 + 7];
    const float wx0_int = Wih_int[lane * 2 + 0];
    const float wx1_int = Wih_int[lane * 2 + 1];
    const float b_int = bih_int[lane] + bhh_int[lane];
    // rows 16..23 are the g-gate -> tanh(x) = 2*sigmoid(2x) - 1
    const bool is_g = (lane >= 16) && (lane < 24);
    const float pre = is_g ? 2.0f : 1.0f;
    const float scl = is_g ? 2.0f : 1.0f;
    const float off = is_g ? -1.0f : 0.0f;

    // output head: W_out [2, 40]; emb = [h_his(32), h_int(8)]
    const float wo0  = W_out[lane];
    const float wo1  = W_out[40 + lane];
    const float wo0i = (lane < 8) ? W_out[32 + lane] : 0.0f;
    const float wo1i = (lane < 8) ? W_out[72 + lane] : 0.0f;

    int a0 = t - (L_WIN - 1);
    if (a0 < 0) a0 = 0;

    float h = 0.0f, c = 0.0f;   // his unit `lane`
    float hi = 0.0f, ci = 0.0f; // int unit (lane & 7), authoritative lanes 0..7
    const int u8 = lane & 7;

    // prefill broadcast slot 0 with zero state
    ((ull*)hb[0][w])[lane] = 0ULL;
    if (lane < 8) ib[0][w][lane] = 0.0f;
    int p = 0;

    const float2* __restrict__ inp2 = (const float2*)inputs; // [T,B,N] float2
    long base = ((long)a0 * B_DIM + b) * N_DIM;
    float2 xh = inp2[base + 3]; // node -1 -> index 3
    float2 xi = inp2[base + 0]; // node 0

    for (int a = a0; a <= t; a++) {
        __syncwarp();

        const ulonglong2* __restrict__ hb4 = hb[p][w];
        float4 hiA = *(const float4*)&ib[p][w][0];
        float4 hiB = *(const float4*)&ib[p][w][4];

        // --- his gates: packed (i,f) and (g,o), 4-way split accumulators ---
        ull x0 = pack2(xh.x, xh.x);
        ull x1 = pack2(xh.y, xh.y);
        ull aif[4], ago[4];
        aif[0] = fma2(x0, wx0_if, bb_if);
        aif[1] = fma2(x1, wx1_if, 0ULL);
        aif[2] = 0ULL; aif[3] = 0ULL;
        ago[0] = fma2(x0, wx0_go, bb_go);
        ago[1] = fma2(x1, wx1_go, 0ULL);
        ago[2] = 0ULL; ago[3] = 0ULL;
#pragma unroll
        for (int j = 0; j < 16; j++) {
            ulonglong2 hv = hb4[j];              // uniform LDS.128 broadcast
            const int k0 = 2 * j, k1 = 2 * j + 1;
            aif[k0 & 3] = fma2(hv.x, w_if[k0], aif[k0 & 3]);
            ago[k0 & 3] = fma2(hv.x, w_go[k0], ago[k0 & 3]);
            aif[k1 & 3] = fma2(hv.y, w_if[k1], aif[k1 & 3]);
            ago[k1 & 3] = fma2(hv.y, w_go[k1], ago[k1 & 3]);
        }
        ull AIF = add2(add2(aif[0], aif[1]), add2(aif[2], aif[3]));
        ull AGO = add2(add2(ago[0], ago[1]), add2(ago[2], ago[3]));

        // --- int gate row (scalar per lane) ---
        float g0 = fmaf(xi.x, wx0_int, fmaf(xi.y, wx1_int, b_int));
        float g1 = fmaf(hiA.y, wi1, hiA.z * wi2);
        g0 = fmaf(hiA.x, wi0, g0);
        g1 = fmaf(hiA.w, wi3, g1);
        g0 = fmaf(hiB.x, wi4, g0);
        g1 = fmaf(hiB.y, wi5, g1);
        g0 = fmaf(hiB.z, wi6, g0);
        g1 = fmaf(hiB.w, wi7, g1);
        float gint = g0 + g1;

        // --- prefetch next step's inputs ---
        float2 xh_n = xh, xi_n = xi;
        if (a < t) {
            long nb = ((long)(a + 1) * B_DIM + b) * N_DIM;
            xh_n = inp2[nb + 3];
            xi_n = inp2[nb + 0];
        }

        // --- his activations & state update ---
        float gi, gf, gg, go;
        unpack2(AIF, gi, gf);
        unpack2(AGO, gg, go);
        float si = sigf(gi), sf = sigf(gf), tg = tanh_fast(gg), so = sigf(go);
        c = fmaf(sf, c, si * tg);
        h = so * tanh_fast(c);
        ((ull*)hb[p ^ 1][w])[lane] = pack2(h, h);   // STS.64, next slot

        // --- int activations: one sigmoid per gate row, gather per unit ---
        float actv = fmaf(scl, sigf(pre * gint), off);
        float ii = __shfl_sync(FULL, actv, u8);
        float ff = __shfl_sync(FULL, actv, u8 + 8);
        float g2 = __shfl_sync(FULL, actv, u8 + 16);
        float oo = __shfl_sync(FULL, actv, u8 + 24);
        ci = fmaf(ff, ci, ii * g2);
        hi = oo * tanh_fast(ci);
        if (lane < 8) ib[p ^ 1][w][lane] = hi;

        p ^= 1;
        xh = xh_n;
        xi = xi_n;
    }

    // ---- output head: warp reduction over the 40-dim embedding ----
    float s0 = fmaf(h, wo0, hi * wo0i);
    float s1 = fmaf(h, wo1, hi * wo1i);
#pragma unroll
    for (int d = 16; d > 0; d >>= 1) {
        s0 += __shfl_xor_sync(FULL, s0, d);
        s1 += __shfl_xor_sync(FULL, s1, d);
    }
    if (lane == 0) {
        float2 o;
        o.x = s0 + b_out[0];
        o.y = s1 + b_out[1];
        ((float2*)out)[t * B_DIM + b] = o;
    }
}

extern "C" void kernel_launch(void* const* d_in, const int* in_sizes, int n_in,
                              void* d_out, int out_size) {
    (void)in_sizes; (void)n_in; (void)out_size;
    const float* inputs  = (const float*)d_in[0];
    const float* Wih_his = (const float*)d_in[1];
    const float* Whh_his = (const float*)d_in[2];
    const float* bih_his = (const float*)d_in[3];
    const float* bhh_his = (const float*)d_in[4];
    const float* Wih_int = (const float*)d_in[5];
    const float* Whh_int = (const float*)d_in[6];
    const float* bih_int = (const float*)d_in[7];
    const float* bhh_int = (const float*)d_in[8];
    const float* W_out   = (const float*)d_in[9];
    const float* b_out   = (const float*)d_in[10];
    float* out = (float*)d_out;

    // 32768 sequences, one warp each: 10 warps (320 threads) per block
    int nblocks = (NWARPS_TOTAL + WARPS_PB - 1) / WARPS_PB;
    traj_kernel<<<nblocks, THREADS>>>(inputs, Wih_his, Whh_his, bih_his, bhh_his,
                                      Wih_int, Whh_int, bih_int, bhh_int,
                                      W_out, b_out, out);
}

// round 6
// speedup vs baseline: 1.9986x; 1.9986x over previous
#include <cuda_runtime.h>
#include <cstdint>

#define T_DIM 256
#define B_DIM 128
#define N_DIM 4
#define L_WIN 64
#define WARPS_PB 8
#define THREADS (WARPS_PB * 32)
#define NWARPS_TOTAL (T_DIM * B_DIM)

typedef unsigned long long ull;

// ---------- f32x2 packed helpers (sm_100+) ----------
__device__ __forceinline__ ull pack2(float lo, float hi) {
    ull r;
    asm("mov.b64 %0, {%1, %2};" : "=l"(r) : "f"(lo), "f"(hi));
    return r;
}
__device__ __forceinline__ void unpack2(ull v, float& lo, float& hi) {
    asm("mov.b64 {%0, %1}, %2;" : "=f"(lo), "=f"(hi) : "l"(v));
}
__device__ __forceinline__ ull fma2(ull a, ull b, ull c) {
    ull d;
    asm("fma.rn.f32x2 %0, %1, %2, %3;" : "=l"(d) : "l"(a), "l"(b), "l"(c));
    return d;
}

// ---------- fast activations (MUFU EX2 + RCP) ----------
__device__ __forceinline__ float sigf(float x) {
    float e = __expf(-x);
    return __fdividef(1.0f, 1.0f + e);
}
__device__ __forceinline__ float tanh_fast(float x) {
    float e = __expf(2.0f * x);
    return 1.0f - __fdividef(2.0f, e + 1.0f);
}

// One warp per (t, b) sequence. Lane u owns hidden unit u of the H=32 "his"
// LSTM. h is exchanged via mirrored shared buffers read with per-lane ROTATED
// LDS.64 pairs: for each j, lanes hit 16 distinct 8B slots of one 128B line
// (conflict-free, 1 wavefront). Weights are packed in each lane's rotation
// order at load time, so the inner loop is pure LDS.64 + fma.rn.f32x2.
__global__ void __launch_bounds__(THREADS, 1) traj_kernel(
    const float* __restrict__ inputs,
    const float* __restrict__ Wih_his, const float* __restrict__ Whh_his,
    const float* __restrict__ bih_his, const float* __restrict__ bhh_his,
    const float* __restrict__ Wih_int, const float* __restrict__ Whh_int,
    const float* __restrict__ bih_int, const float* __restrict__ bhh_int,
    const float* __restrict__ W_out, const float* __restrict__ b_out,
    float* __restrict__ out)
{
    // ping-pong, mirrored broadcast buffers (ull-typed for 8B alignment)
    __shared__ ull hsm[WARPS_PB][2][32]; // 32 h + 32 mirror (as 32 ull = 64 f32)
    __shared__ ull ism[WARPS_PB][2][8];  // 8 h_int + 8 mirror

    const unsigned FULL = 0xffffffffu;
    const int lane = threadIdx.x & 31;
    const int w = threadIdx.x >> 5;
    const int gw = blockIdx.x * WARPS_PB + w;

    const int t = (T_DIM - 1) - (gw >> 7);   // long windows scheduled first
    const int b = gw & (B_DIM - 1);

    // ---- his weights, pre-rotated & pair-packed ----
    // gate rows: i=lane, f=32+lane, g=64+lane, o=96+lane (Whh_his [128,32])
    const int r = lane & 15;            // pair-rotation base
    ull w_i[16], w_f[16], w_g[16], w_o[16];
#pragma unroll
    for (int j = 0; j < 16; j++) {
        int p = (r + j) & 15;
        w_i[j] = pack2(Whh_his[(lane)      * 32 + 2 * p], Whh_his[(lane)      * 32 + 2 * p + 1]);
        w_f[j] = pack2(Whh_his[(32 + lane) * 32 + 2 * p], Whh_his[(32 + lane) * 32 + 2 * p + 1]);
        w_g[j] = pack2(Whh_his[(64 + lane) * 32 + 2 * p], Whh_his[(64 + lane) * 32 + 2 * p + 1]);
        w_o[j] = pack2(Whh_his[(96 + lane) * 32 + 2 * p], Whh_his[(96 + lane) * 32 + 2 * p + 1]);
    }
    // x-weights as (wx0, wx1) pairs, bias as (bias, 0) addend
    ull wx_i = pack2(Wih_his[(lane) * 2],      Wih_his[(lane) * 2 + 1]);
    ull wx_f = pack2(Wih_his[(32 + lane) * 2], Wih_his[(32 + lane) * 2 + 1]);
    ull wx_g = pack2(Wih_his[(64 + lane) * 2], Wih_his[(64 + lane) * 2 + 1]);
    ull wx_o = pack2(Wih_his[(96 + lane) * 2], Wih_his[(96 + lane) * 2 + 1]);
    ull b_i = pack2(bih_his[lane]      + bhh_his[lane],      0.0f);
    ull b_f = pack2(bih_his[32 + lane] + bhh_his[32 + lane], 0.0f);
    ull b_g = pack2(bih_his[64 + lane] + bhh_his[64 + lane], 0.0f);
    ull b_o = pack2(bih_his[96 + lane] + bhh_his[96 + lane], 0.0f);

    // ---- int weights (lane = gate row, H=8), rotated pairs ----
    const int q = lane & 3;
    ull wq[4];
#pragma unroll
    for (int j = 0; j < 4; j++) {
        int p = (q + j) & 3;
        wq[j] = pack2(Whh_int[lane * 8 + 2 * p], Whh_int[lane * 8 + 2 * p + 1]);
    }
    ull wxi = pack2(Wih_int[lane * 2], Wih_int[lane * 2 + 1]);
    ull bi2 = pack2(bih_int[lane] + bhh_int[lane], 0.0f);
    // rows 16..23 are the g-gate -> tanh(x) = 2*sigmoid(2x) - 1
    const bool is_g = (lane >= 16) && (lane < 24);
    const float pre = is_g ? 2.0f : 1.0f;
    const float scl = is_g ? 2.0f : 1.0f;
    const float off = is_g ? -1.0f : 0.0f;

    // output head: W_out [2, 40]; emb = [h_his(32), h_int(8)]
    const float wo0  = W_out[lane];
    const float wo1  = W_out[40 + lane];
    const float wo0i = (lane < 8) ? W_out[32 + lane] : 0.0f;
    const float wo1i = (lane < 8) ? W_out[72 + lane] : 0.0f;

    int a0 = t - (L_WIN - 1);
    if (a0 < 0) a0 = 0;

    float h = 0.0f, c = 0.0f;   // his unit `lane`
    float hin = 0.0f, cin = 0.0f; // int unit (lane & 7), redundant across groups
    const int u8 = lane & 7;

    // zero-fill broadcast slot 0
    hsm[w][0][lane] = 0ULL;
    if (lane < 8) ism[w][0][lane] = 0ULL;
    int pp = 0;

    const float2* __restrict__ inp2 = (const float2*)inputs; // [T,B,N] of float2
    long base = ((long)a0 * B_DIM + b) * N_DIM;
    float2 xh = inp2[base + 3]; // node -1 -> index 3
    float2 xi = inp2[base + 0]; // node 0

    for (int a = a0; a <= t; a++) {
        __syncwarp();

        const ull* __restrict__ hbr = hsm[w][pp] + r;   // rotated base (8B units)
        const ull* __restrict__ ibr = ism[w][pp] + q;

        // --- his gates: 4 pair-k accumulators ---
        ull xh2 = pack2(xh.x, xh.y);
        ull ai = fma2(xh2, wx_i, b_i);
        ull af = fma2(xh2, wx_f, b_f);
        ull ag = fma2(xh2, wx_g, b_g);
        ull ao = fma2(xh2, wx_o, b_o);
#pragma unroll
        for (int j = 0; j < 16; j++) {
            ull hp = hbr[j];                 // LDS.64, conflict-free rotated
            ai = fma2(hp, w_i[j], ai);
            af = fma2(hp, w_f[j], af);
            ag = fma2(hp, w_g[j], ag);
            ao = fma2(hp, w_o[j], ao);
        }

        // --- int gate row ---
        ull xi2 = pack2(xi.x, xi.y);
        ull aint = fma2(xi2, wxi, bi2);
#pragma unroll
        for (int j = 0; j < 4; j++)
            aint = fma2(ibr[j], wq[j], aint);

        // --- prefetch next step's inputs ---
        float2 xh_n = xh, xi_n = xi;
        if (a < t) {
            long nb = ((long)(a + 1) * B_DIM + b) * N_DIM;
            xh_n = inp2[nb + 3];
            xi_n = inp2[nb + 0];
        }

        // --- his fold + activations + state update ---
        float l0, h0, l1, h1, l2, h2, l3, h3;
        unpack2(ai, l0, h0);
        unpack2(af, l1, h1);
        unpack2(ag, l2, h2);
        unpack2(ao, l3, h3);
        float si = sigf(l0 + h0), sf = sigf(l1 + h1);
        float tg = tanh_fast(l2 + h2), so = sigf(l3 + h3);
        c = fmaf(sf, c, si * tg);
        h = so * tanh_fast(c);
        // publish h (value + mirror) for next step
        float* hn = (float*)hsm[w][pp ^ 1];
        hn[lane] = h;
        hn[lane + 32] = h;

        // --- int fold + activations ---
        float li, hi2;
        unpack2(aint, li, hi2);
        float actv = fmaf(scl, sigf(pre * (li + hi2)), off);
        float ii = __shfl_sync(FULL, actv, u8);
        float ff = __shfl_sync(FULL, actv, u8 + 8);
        float g2 = __shfl_sync(FULL, actv, u8 + 16);
        float oo = __shfl_sync(FULL, actv, u8 + 24);
        cin = fmaf(ff, cin, ii * g2);
        hin = oo * tanh_fast(cin);
        float* in_ = (float*)ism[w][pp ^ 1];
        if (lane < 16) in_[lane] = hin;   // slots 0..15, slot s = h_int[s&7]

        pp ^= 1;
        xh = xh_n;
        xi = xi_n;
    }

    // ---- output head: warp reduction over the 40-dim embedding ----
    float s0 = fmaf(h, wo0, hin * wo0i);
    float s1 = fmaf(h, wo1, hin * wo1i);
#pragma unroll
    for (int d = 16; d > 0; d >>= 1) {
        s0 += __shfl_xor_sync(FULL, s0, d);
        s1 += __shfl_xor_sync(FULL, s1, d);
    }
    if (lane == 0) {
        float2 o;
        o.x = s0 + b_out[0];
        o.y = s1 + b_out[1];
        ((float2*)out)[t * B_DIM + b] = o;
    }
}

extern "C" void kernel_launch(void* const* d_in, const int* in_sizes, int n_in,
                              void* d_out, int out_size) {
    (void)in_sizes; (void)n_in; (void)out_size;
    const float* inputs  = (const float*)d_in[0];
    const float* Wih_his = (const float*)d_in[1];
    const float* Whh_his = (const float*)d_in[2];
    const float* bih_his = (const float*)d_in[3];
    const float* bhh_his = (const float*)d_in[4];
    const float* Wih_int = (const float*)d_in[5];
    const float* Whh_int = (const float*)d_in[6];
    const float* bih_int = (const float*)d_in[7];
    const float* bhh_int = (const float*)d_in[8];
    const float* W_out   = (const float*)d_in[9];
    const float* b_out   = (const float*)d_in[10];
    float* out = (float*)d_out;

    // 32768 sequences, one warp each: 8 warps (256 threads) per block
    traj_kernel<<<NWARPS_TOTAL / WARPS_PB, THREADS>>>(
        inputs, Wih_his, Whh_his, bih_his, bhh_his,
        Wih_int, Whh_int, bih_int, bhh_int,
        W_out, b_out, out);
}

// round 7
// speedup vs baseline: 2.5130x; 1.2574x over previous
#include <cuda_runtime.h>
#include <cstdint>

#define T_DIM 256
#define B_DIM 128
#define N_DIM 4
#define L_WIN 64
#define WARPS_PB 8
#define THREADS (WARPS_PB * 32)
#define SEQ_PW 2
#define NW (T_DIM * B_DIM / SEQ_PW)   // 16384 warps, 2 sequences each

typedef unsigned long long ull;

// ---------- f32x2 packed helpers (sm_100+) ----------
__device__ __forceinline__ ull pack2(float lo, float hi) {
    ull r;
    asm("mov.b64 %0, {%1, %2};" : "=l"(r) : "f"(lo), "f"(hi));
    return r;
}
__device__ __forceinline__ void unpack2(ull v, float& lo, float& hi) {
    asm("mov.b64 {%0, %1}, %2;" : "=f"(lo), "=f"(hi) : "l"(v));
}
__device__ __forceinline__ ull fma2(ull a, ull b, ull c) {
    ull d;
    asm("fma.rn.f32x2 %0, %1, %2, %3;" : "=l"(d) : "l"(a), "l"(b), "l"(c));
    return d;
}

// ---------- fast activations (MUFU EX2 + RCP) ----------
__device__ __forceinline__ float sigf(float x) {
    float e = __expf(-x);
    return __fdividef(1.0f, 1.0f + e);
}
__device__ __forceinline__ float tanh_fast(float x) {
    float e = __expf(2.0f * x);
    return 1.0f - __fdividef(2.0f, e + 1.0f);
}

// One warp per TWO (t, b) sequences (same t, adjacent b) — weight registers
// are shared, doubling ILP at ~zero register cost. Lane u owns hidden unit u
// of the H=32 "his" LSTM. h exchanged via mirrored smem read with per-lane
// rotated LDS.128 (8 distinct 16B slots -> 1 conflict-free wavefront).
__global__ void __launch_bounds__(THREADS, 1) traj_kernel(
    const float* __restrict__ inputs,
    const float* __restrict__ Wih_his, const float* __restrict__ Whh_his,
    const float* __restrict__ bih_his, const float* __restrict__ bhh_his,
    const float* __restrict__ Wih_int, const float* __restrict__ Whh_int,
    const float* __restrict__ bih_int, const float* __restrict__ bhh_int,
    const float* __restrict__ W_out, const float* __restrict__ b_out,
    float* __restrict__ out)
{
    // ping-pong, mirrored broadcast buffers
    __shared__ ulonglong2 hsm[WARPS_PB][SEQ_PW][2][16]; // 32 h + 32 mirror (f32)
    __shared__ ulonglong2 ism[WARPS_PB][SEQ_PW][2][4];  // 8 h_int + 8 mirror

    const unsigned FULL = 0xffffffffu;
    const int lane = threadIdx.x & 31;
    const int w = threadIdx.x >> 5;
    const int gw = blockIdx.x * WARPS_PB + w;

    const int t = (T_DIM - 1) - (gw >> 6);          // long windows first
    const int b0 = (gw & 63) * 2;                   // two adjacent batch rows

    // ---- his weights: rotated 16B-slot packing ----
    // slot sp holds h[4sp..4sp+3]; lane reads slots (r2+j)&7 via mirror.
    const int r2 = lane & 7;
    ull wAi[8], wBi[8], wAf[8], wBf[8], wAg[8], wBg[8], wAo[8], wBo[8];
#pragma unroll
    for (int j = 0; j < 8; j++) {
        int sp = (r2 + j) & 7;
        const float* Ri = Whh_his + (lane)      * 32 + 4 * sp;
        const float* Rf = Whh_his + (32 + lane) * 32 + 4 * sp;
        const float* Rg = Whh_his + (64 + lane) * 32 + 4 * sp;
        const float* Ro = Whh_his + (96 + lane) * 32 + 4 * sp;
        wAi[j] = pack2(Ri[0], Ri[1]); wBi[j] = pack2(Ri[2], Ri[3]);
        wAf[j] = pack2(Rf[0], Rf[1]); wBf[j] = pack2(Rf[2], Rf[3]);
        wAg[j] = pack2(Rg[0], Rg[1]); wBg[j] = pack2(Rg[2], Rg[3]);
        wAo[j] = pack2(Ro[0], Ro[1]); wBo[j] = pack2(Ro[2], Ro[3]);
    }
    ull wx_i = pack2(Wih_his[(lane) * 2],      Wih_his[(lane) * 2 + 1]);
    ull wx_f = pack2(Wih_his[(32 + lane) * 2], Wih_his[(32 + lane) * 2 + 1]);
    ull wx_g = pack2(Wih_his[(64 + lane) * 2], Wih_his[(64 + lane) * 2 + 1]);
    ull wx_o = pack2(Wih_his[(96 + lane) * 2], Wih_his[(96 + lane) * 2 + 1]);
    ull b_i = pack2(bih_his[lane]      + bhh_his[lane],      0.0f);
    ull b_f = pack2(bih_his[32 + lane] + bhh_his[32 + lane], 0.0f);
    ull b_g = pack2(bih_his[64 + lane] + bhh_his[64 + lane], 0.0f);
    ull b_o = pack2(bih_his[96 + lane] + bhh_his[96 + lane], 0.0f);

    // ---- int weights (lane = gate row, H=8): 2 rotated 16B slots ----
    const int q2 = lane & 1;
    ull wqA[2], wqB[2];
#pragma unroll
    for (int j = 0; j < 2; j++) {
        int sp = (q2 + j) & 1;
        const float* R = Whh_int + lane * 8 + 4 * sp;
        wqA[j] = pack2(R[0], R[1]);
        wqB[j] = pack2(R[2], R[3]);
    }
    ull wxi = pack2(Wih_int[lane * 2], Wih_int[lane * 2 + 1]);
    ull bi2 = pack2(bih_int[lane] + bhh_int[lane], 0.0f);
    // rows 16..23 are the g-gate -> tanh(x) = 2*sigmoid(2x) - 1
    const bool is_g = (lane >= 16) && (lane < 24);
    const float pre = is_g ? 2.0f : 1.0f;
    const float scl = is_g ? 2.0f : 1.0f;
    const float off = is_g ? -1.0f : 0.0f;

    // output head: W_out [2, 40]; emb = [h_his(32), h_int(8)]
    const float wo0  = W_out[lane];
    const float wo1  = W_out[40 + lane];
    const float wo0i = (lane < 8) ? W_out[32 + lane] : 0.0f;
    const float wo1i = (lane < 8) ? W_out[72 + lane] : 0.0f;

    int a0 = t - (L_WIN - 1);
    if (a0 < 0) a0 = 0;

    float h0 = 0.0f, c0 = 0.0f, h1 = 0.0f, c1 = 0.0f;
    float hn0 = 0.0f, cn0 = 0.0f, hn1 = 0.0f, cn1 = 0.0f; // int states
    const int u8 = lane & 7;

    // zero-fill broadcast slot 0 for both sequences
    {
        float* z0 = (float*)hsm[w][0][0];
        float* z1 = (float*)hsm[w][1][0];
        z0[lane] = 0.0f; z0[lane + 32] = 0.0f;
        z1[lane] = 0.0f; z1[lane + 32] = 0.0f;
        if (lane < 16) {
            ((float*)ism[w][0][0])[lane] = 0.0f;
            ((float*)ism[w][1][0])[lane] = 0.0f;
        }
    }
    int pp = 0;

    const float2* __restrict__ inp2 = (const float2*)inputs; // [T,B,N] of float2
    long idx = ((long)a0 * B_DIM + b0) * N_DIM;
    const long STRIDE = (long)B_DIM * N_DIM;

    for (int a = a0; a <= t; a++, idx += STRIDE) {
        __syncwarp();

        // inputs for both sequences (consumed after the h-loop -> latency hidden)
        float2 xh0 = inp2[idx + 3],          xi0 = inp2[idx + 0];
        float2 xh1 = inp2[idx + N_DIM + 3],  xi1 = inp2[idx + N_DIM + 0];

        const ulonglong2* __restrict__ hb0 = hsm[w][0][pp] + r2;
        const ulonglong2* __restrict__ hb1 = hsm[w][1][pp] + r2;
        const ulonglong2* __restrict__ ib0 = ism[w][0][pp] + q2;
        const ulonglong2* __restrict__ ib1 = ism[w][1][pp] + q2;

        // --- his gates, both sequences ---
        ull ai0 = b_i, af0 = b_f, ag0 = b_g, ao0 = b_o;
        ull ai1 = b_i, af1 = b_f, ag1 = b_g, ao1 = b_o;
#pragma unroll
        for (int j = 0; j < 8; j++) {
            ulonglong2 v0 = hb0[j];           // 1 conflict-free wavefront
            ulonglong2 v1 = hb1[j];
            ai0 = fma2(v0.x, wAi[j], ai0); ai0 = fma2(v0.y, wBi[j], ai0);
            af0 = fma2(v0.x, wAf[j], af0); af0 = fma2(v0.y, wBf[j], af0);
            ag0 = fma2(v0.x, wAg[j], ag0); ag0 = fma2(v0.y, wBg[j], ag0);
            ao0 = fma2(v0.x, wAo[j], ao0); ao0 = fma2(v0.y, wBo[j], ao0);
            ai1 = fma2(v1.x, wAi[j], ai1); ai1 = fma2(v1.y, wBi[j], ai1);
            af1 = fma2(v1.x, wAf[j], af1); af1 = fma2(v1.y, wBf[j], af1);
            ag1 = fma2(v1.x, wAg[j], ag1); ag1 = fma2(v1.y, wBg[j], ag1);
            ao1 = fma2(v1.x, wAo[j], ao1); ao1 = fma2(v1.y, wBo[j], ao1);
        }
        ai0 = fma2(pack2(xh0.x, xh0.y), wx_i, ai0);
        af0 = fma2(pack2(xh0.x, xh0.y), wx_f, af0);
        ag0 = fma2(pack2(xh0.x, xh0.y), wx_g, ag0);
        ao0 = fma2(pack2(xh0.x, xh0.y), wx_o, ao0);
        ai1 = fma2(pack2(xh1.x, xh1.y), wx_i, ai1);
        af1 = fma2(pack2(xh1.x, xh1.y), wx_f, af1);
        ag1 = fma2(pack2(xh1.x, xh1.y), wx_g, ag1);
        ao1 = fma2(pack2(xh1.x, xh1.y), wx_o, ao1);

        // --- int gate rows ---
        ull n0 = bi2, n1 = bi2;
#pragma unroll
        for (int j = 0; j < 2; j++) {
            ulonglong2 u0 = ib0[j];
            ulonglong2 u1 = ib1[j];
            n0 = fma2(u0.x, wqA[j], n0); n0 = fma2(u0.y, wqB[j], n0);
            n1 = fma2(u1.x, wqA[j], n1); n1 = fma2(u1.y, wqB[j], n1);
        }
        n0 = fma2(pack2(xi0.x, xi0.y), wxi, n0);
        n1 = fma2(pack2(xi1.x, xi1.y), wxi, n1);

        // --- his fold + activations + state update, seq 0 ---
        float l, hfold;
        unpack2(ai0, l, hfold); float si = sigf(l + hfold);
        unpack2(af0, l, hfold); float sf = sigf(l + hfold);
        unpack2(ag0, l, hfold); float tg = tanh_fast(l + hfold);
        unpack2(ao0, l, hfold); float so = sigf(l + hfold);
        c0 = fmaf(sf, c0, si * tg);
        h0 = so * tanh_fast(c0);
        float* hp0 = (float*)hsm[w][0][pp ^ 1];
        hp0[lane] = h0; hp0[lane + 32] = h0;

        // --- seq 1 ---
        unpack2(ai1, l, hfold); si = sigf(l + hfold);
        unpack2(af1, l, hfold); sf = sigf(l + hfold);
        unpack2(ag1, l, hfold); tg = tanh_fast(l + hfold);
        unpack2(ao1, l, hfold); so = sigf(l + hfold);
        c1 = fmaf(sf, c1, si * tg);
        h1 = so * tanh_fast(c1);
        float* hp1 = (float*)hsm[w][1][pp ^ 1];
        hp1[lane] = h1; hp1[lane + 32] = h1;

        // --- int activations, both sequences ---
        unpack2(n0, l, hfold);
        float a0v = fmaf(scl, sigf(pre * (l + hfold)), off);
        unpack2(n1, l, hfold);
        float a1v = fmaf(scl, sigf(pre * (l + hfold)), off);
        float i0g = __shfl_sync(FULL, a0v, u8);
        float f0g = __shfl_sync(FULL, a0v, u8 + 8);
        float g0g = __shfl_sync(FULL, a0v, u8 + 16);
        float o0g = __shfl_sync(FULL, a0v, u8 + 24);
        float i1g = __shfl_sync(FULL, a1v, u8);
        float f1g = __shfl_sync(FULL, a1v, u8 + 8);
        float g1g = __shfl_sync(FULL, a1v, u8 + 16);
        float o1g = __shfl_sync(FULL, a1v, u8 + 24);
        cn0 = fmaf(f0g, cn0, i0g * g0g);
        hn0 = o0g * tanh_fast(cn0);
        cn1 = fmaf(f1g, cn1, i1g * g1g);
        hn1 = o1g * tanh_fast(cn1);
        if (lane < 16) {
            ((float*)ism[w][0][pp ^ 1])[lane] = hn0;
            ((float*)ism[w][1][pp ^ 1])[lane] = hn1;
        }

        pp ^= 1;
    }

    // ---- output head: warp reductions over the 40-dim embedding ----
    float s00 = fmaf(h0, wo0, hn0 * wo0i);
    float s01 = fmaf(h0, wo1, hn0 * wo1i);
    float s10 = fmaf(h1, wo0, hn1 * wo0i);
    float s11 = fmaf(h1, wo1, hn1 * wo1i);
#pragma unroll
    for (int d = 16; d > 0; d >>= 1) {
        s00 += __shfl_xor_sync(FULL, s00, d);
        s01 += __shfl_xor_sync(FULL, s01, d);
        s10 += __shfl_xor_sync(FULL, s10, d);
        s11 += __shfl_xor_sync(FULL, s11, d);
    }
    if (lane == 0) {
        float2 o0; o0.x = s00 + b_out[0]; o0.y = s01 + b_out[1];
        float2 o1; o1.x = s10 + b_out[0]; o1.y = s11 + b_out[1];
        ((float2*)out)[t * B_DIM + b0]     = o0;
        ((float2*)out)[t * B_DIM + b0 + 1] = o1;
    }
}

extern "C" void kernel_launch(void* const* d_in, const int* in_sizes, int n_in,
                              void* d_out, int out_size) {
    (void)in_sizes; (void)n_in; (void)out_size;
    const float* inputs  = (const float*)d_in[0];
    const float* Wih_his = (const float*)d_in[1];
    const float* Whh_his = (const float*)d_in[2];
    const float* bih_his = (const float*)d_in[3];
    const float* bhh_his = (const float*)d_in[4];
    const float* Wih_int = (const float*)d_in[5];
    const float* Whh_int = (const float*)d_in[6];
    const float* bih_int = (const float*)d_in[7];
    const float* bhh_int = (const float*)d_in[8];
    const float* W_out   = (const float*)d_in[9];
    const float* b_out   = (const float*)d_in[10];
    float* out = (float*)d_out;

    traj_kernel<<<NW / WARPS_PB, THREADS>>>(
        inputs, Wih_his, Whh_his, bih_his, bhh_his,
        Wih_int, Whh_int, bih_int, bhh_int,
        W_out, b_out, out);
}

// round 8
// speedup vs baseline: 2.8731x; 1.1433x over previous
#include <cuda_runtime.h>
#include <cstdint>

#define T_DIM 256
#define B_DIM 128
#define N_DIM 4
#define L_WIN 64
#define WARPS_PB 8
#define THREADS (WARPS_PB * 32)
#define SEQ_PW 2
#define NW (T_DIM * B_DIM / SEQ_PW)   // 16384 warps, 2 sequences each

typedef unsigned long long ull;

// ---------- f32x2 packed helpers (sm_100+) ----------
__device__ __forceinline__ ull pack2(float lo, float hi) {
    ull r;
    asm("mov.b64 %0, {%1, %2};" : "=l"(r) : "f"(lo), "f"(hi));
    return r;
}
__device__ __forceinline__ void unpack2(ull v, float& lo, float& hi) {
    asm("mov.b64 {%0, %1}, %2;" : "=f"(lo), "=f"(hi) : "l"(v));
}
__device__ __forceinline__ ull fma2(ull a, ull b, ull c) {
    ull d;
    asm("fma.rn.f32x2 %0, %1, %2, %3;" : "=l"(d) : "l"(a), "l"(b), "l"(c));
    return d;
}

// ---------- single-MUFU activations (MUFU.TANH, sm_75+) ----------
__device__ __forceinline__ float tanh_a(float x) {
    float y;
    asm("tanh.approx.f32 %0, %1;" : "=f"(y) : "f"(x));
    return y;
}
__device__ __forceinline__ float sig_a(float x) {
    return fmaf(0.5f, tanh_a(0.5f * x), 0.5f);
}

// One warp per TWO (t, b) sequences (same t, adjacent b) — weight registers
// are shared, doubling ILP at ~zero register cost. Lane u owns hidden unit u
// of the H=32 "his" LSTM. h exchanged via mirrored smem read with per-lane
// rotated LDS.128 (8 distinct 16B slots -> 1 conflict-free wavefront).
__global__ void __launch_bounds__(THREADS, 1) traj_kernel(
    const float* __restrict__ inputs,
    const float* __restrict__ Wih_his, const float* __restrict__ Whh_his,
    const float* __restrict__ bih_his, const float* __restrict__ bhh_his,
    const float* __restrict__ Wih_int, const float* __restrict__ Whh_int,
    const float* __restrict__ bih_int, const float* __restrict__ bhh_int,
    const float* __restrict__ W_out, const float* __restrict__ b_out,
    float* __restrict__ out)
{
    // ping-pong, mirrored broadcast buffers
    __shared__ ulonglong2 hsm[WARPS_PB][SEQ_PW][2][16]; // 32 h + 32 mirror (f32)
    __shared__ ulonglong2 ism[WARPS_PB][SEQ_PW][2][4];  // 8 h_int + 8 mirror

    const unsigned FULL = 0xffffffffu;
    const int lane = threadIdx.x & 31;
    const int w = threadIdx.x >> 5;
    const int gw = blockIdx.x * WARPS_PB + w;

    const int t = (T_DIM - 1) - (gw >> 6);          // long windows first
    const int b0 = (gw & 63) * 2;                   // two adjacent batch rows

    // ---- his weights: rotated 16B-slot packing ----
    // slot sp holds h[4sp..4sp+3]; lane reads slots (r2+j)&7 via mirror.
    const int r2 = lane & 7;
    ull wAi[8], wBi[8], wAf[8], wBf[8], wAg[8], wBg[8], wAo[8], wBo[8];
#pragma unroll
    for (int j = 0; j < 8; j++) {
        int sp = (r2 + j) & 7;
        const float* Ri = Whh_his + (lane)      * 32 + 4 * sp;
        const float* Rf = Whh_his + (32 + lane) * 32 + 4 * sp;
        const float* Rg = Whh_his + (64 + lane) * 32 + 4 * sp;
        const float* Ro = Whh_his + (96 + lane) * 32 + 4 * sp;
        wAi[j] = pack2(Ri[0], Ri[1]); wBi[j] = pack2(Ri[2], Ri[3]);
        wAf[j] = pack2(Rf[0], Rf[1]); wBf[j] = pack2(Rf[2], Rf[3]);
        wAg[j] = pack2(Rg[0], Rg[1]); wBg[j] = pack2(Rg[2], Rg[3]);
        wAo[j] = pack2(Ro[0], Ro[1]); wBo[j] = pack2(Ro[2], Ro[3]);
    }
    ull wx_i = pack2(Wih_his[(lane) * 2],      Wih_his[(lane) * 2 + 1]);
    ull wx_f = pack2(Wih_his[(32 + lane) * 2], Wih_his[(32 + lane) * 2 + 1]);
    ull wx_g = pack2(Wih_his[(64 + lane) * 2], Wih_his[(64 + lane) * 2 + 1]);
    ull wx_o = pack2(Wih_his[(96 + lane) * 2], Wih_his[(96 + lane) * 2 + 1]);
    ull b_i = pack2(bih_his[lane]      + bhh_his[lane],      0.0f);
    ull b_f = pack2(bih_his[32 + lane] + bhh_his[32 + lane], 0.0f);
    ull b_g = pack2(bih_his[64 + lane] + bhh_his[64 + lane], 0.0f);
    ull b_o = pack2(bih_his[96 + lane] + bhh_his[96 + lane], 0.0f);

    // ---- int weights (lane = gate row, H=8): 2 rotated 16B slots ----
    const int q2 = lane & 1;
    ull wqA[2], wqB[2];
#pragma unroll
    for (int j = 0; j < 2; j++) {
        int sp = (q2 + j) & 1;
        const float* R = Whh_int + lane * 8 + 4 * sp;
        wqA[j] = pack2(R[0], R[1]);
        wqB[j] = pack2(R[2], R[3]);
    }
    ull wxi = pack2(Wih_int[lane * 2], Wih_int[lane * 2 + 1]);
    ull bi2 = pack2(bih_int[lane] + bhh_int[lane], 0.0f);
    // rows 16..23 are the g-gate (tanh); others sigmoid = 0.5*tanh(0.5x)+0.5
    const bool is_g = (lane >= 16) && (lane < 24);
    const float pre = is_g ? 1.0f : 0.5f;
    const float scl = is_g ? 1.0f : 0.5f;
    const float off = is_g ? 0.0f : 0.5f;

    // output head: W_out [2, 40]; emb = [h_his(32), h_int(8)]
    const float wo0  = W_out[lane];
    const float wo1  = W_out[40 + lane];
    const float wo0i = (lane < 8) ? W_out[32 + lane] : 0.0f;
    const float wo1i = (lane < 8) ? W_out[72 + lane] : 0.0f;

    int a0 = t - (L_WIN - 1);
    if (a0 < 0) a0 = 0;

    float h0 = 0.0f, c0 = 0.0f, h1 = 0.0f, c1 = 0.0f;
    float hn0 = 0.0f, cn0 = 0.0f, hn1 = 0.0f, cn1 = 0.0f; // int states
    const int u8 = lane & 7;

    // zero-fill broadcast slot 0 for both sequences
    {
        float* z0 = (float*)hsm[w][0][0];
        float* z1 = (float*)hsm[w][1][0];
        z0[lane] = 0.0f; z0[lane + 32] = 0.0f;
        z1[lane] = 0.0f; z1[lane + 32] = 0.0f;
        if (lane < 16) {
            ((float*)ism[w][0][0])[lane] = 0.0f;
            ((float*)ism[w][1][0])[lane] = 0.0f;
        }
    }
    int pp = 0;

    const float2* __restrict__ inp2 = (const float2*)inputs; // [T,B,N] of float2
    long idx = ((long)a0 * B_DIM + b0) * N_DIM;
    const long STRIDE = (long)B_DIM * N_DIM;

    for (int a = a0; a <= t; a++, idx += STRIDE) {
        __syncwarp();

        // inputs for both sequences (consumed after the h-loop -> latency hidden)
        float2 xh0 = inp2[idx + 3],          xi0 = inp2[idx + 0];
        float2 xh1 = inp2[idx + N_DIM + 3],  xi1 = inp2[idx + N_DIM + 0];

        const ulonglong2* __restrict__ hb0 = hsm[w][0][pp] + r2;
        const ulonglong2* __restrict__ hb1 = hsm[w][1][pp] + r2;
        const ulonglong2* __restrict__ ib0 = ism[w][0][pp] + q2;
        const ulonglong2* __restrict__ ib1 = ism[w][1][pp] + q2;

        // --- his gates, both sequences ---
        ull ai0 = b_i, af0 = b_f, ag0 = b_g, ao0 = b_o;
        ull ai1 = b_i, af1 = b_f, ag1 = b_g, ao1 = b_o;
#pragma unroll
        for (int j = 0; j < 8; j++) {
            ulonglong2 v0 = hb0[j];           // 1 conflict-free wavefront
            ulonglong2 v1 = hb1[j];
            ai0 = fma2(v0.x, wAi[j], ai0); ai0 = fma2(v0.y, wBi[j], ai0);
            af0 = fma2(v0.x, wAf[j], af0); af0 = fma2(v0.y, wBf[j], af0);
            ag0 = fma2(v0.x, wAg[j], ag0); ag0 = fma2(v0.y, wBg[j], ag0);
            ao0 = fma2(v0.x, wAo[j], ao0); ao0 = fma2(v0.y, wBo[j], ao0);
            ai1 = fma2(v1.x, wAi[j], ai1); ai1 = fma2(v1.y, wBi[j], ai1);
            af1 = fma2(v1.x, wAf[j], af1); af1 = fma2(v1.y, wBf[j], af1);
            ag1 = fma2(v1.x, wAg[j], ag1); ag1 = fma2(v1.y, wBg[j], ag1);
            ao1 = fma2(v1.x, wAo[j], ao1); ao1 = fma2(v1.y, wBo[j], ao1);
        }
        ai0 = fma2(pack2(xh0.x, xh0.y), wx_i, ai0);
        af0 = fma2(pack2(xh0.x, xh0.y), wx_f, af0);
        ag0 = fma2(pack2(xh0.x, xh0.y), wx_g, ag0);
        ao0 = fma2(pack2(xh0.x, xh0.y), wx_o, ao0);
        ai1 = fma2(pack2(xh1.x, xh1.y), wx_i, ai1);
        af1 = fma2(pack2(xh1.x, xh1.y), wx_f, af1);
        ag1 = fma2(pack2(xh1.x, xh1.y), wx_g, ag1);
        ao1 = fma2(pack2(xh1.x, xh1.y), wx_o, ao1);

        // --- int gate rows ---
        ull n0 = bi2, n1 = bi2;
#pragma unroll
        for (int j = 0; j < 2; j++) {
            ulonglong2 u0 = ib0[j];
            ulonglong2 u1 = ib1[j];
            n0 = fma2(u0.x, wqA[j], n0); n0 = fma2(u0.y, wqB[j], n0);
            n1 = fma2(u1.x, wqA[j], n1); n1 = fma2(u1.y, wqB[j], n1);
        }
        n0 = fma2(pack2(xi0.x, xi0.y), wxi, n0);
        n1 = fma2(pack2(xi1.x, xi1.y), wxi, n1);

        // --- his fold + activations + state update, seq 0 ---
        float l, hfold;
        unpack2(ai0, l, hfold); float si = sig_a(l + hfold);
        unpack2(af0, l, hfold); float sf = sig_a(l + hfold);
        unpack2(ag0, l, hfold); float tg = tanh_a(l + hfold);
        unpack2(ao0, l, hfold); float so = sig_a(l + hfold);
        c0 = fmaf(sf, c0, si * tg);
        h0 = so * tanh_a(c0);
        float* hp0 = (float*)hsm[w][0][pp ^ 1];
        hp0[lane] = h0; hp0[lane + 32] = h0;

        // --- seq 1 ---
        unpack2(ai1, l, hfold); si = sig_a(l + hfold);
        unpack2(af1, l, hfold); sf = sig_a(l + hfold);
        unpack2(ag1, l, hfold); tg = tanh_a(l + hfold);
        unpack2(ao1, l, hfold); so = sig_a(l + hfold);
        c1 = fmaf(sf, c1, si * tg);
        h1 = so * tanh_a(c1);
        float* hp1 = (float*)hsm[w][1][pp ^ 1];
        hp1[lane] = h1; hp1[lane + 32] = h1;

        // --- int activations, both sequences ---
        unpack2(n0, l, hfold);
        float a0v = fmaf(scl, tanh_a(pre * (l + hfold)), off);
        unpack2(n1, l, hfold);
        float a1v = fmaf(scl, tanh_a(pre * (l + hfold)), off);
        float i0g = __shfl_sync(FULL, a0v, u8);
        float f0g = __shfl_sync(FULL, a0v, u8 + 8);
        float g0g = __shfl_sync(FULL, a0v, u8 + 16);
        float o0g = __shfl_sync(FULL, a0v, u8 + 24);
        float i1g = __shfl_sync(FULL, a1v, u8);
        float f1g = __shfl_sync(FULL, a1v, u8 + 8);
        float g1g = __shfl_sync(FULL, a1v, u8 + 16);
        float o1g = __shfl_sync(FULL, a1v, u8 + 24);
        cn0 = fmaf(f0g, cn0, i0g * g0g);
        hn0 = o0g * tanh_a(cn0);
        cn1 = fmaf(f1g, cn1, i1g * g1g);
        hn1 = o1g * tanh_a(cn1);
        if (lane < 16) {
            ((float*)ism[w][0][pp ^ 1])[lane] = hn0;
            ((float*)ism[w][1][pp ^ 1])[lane] = hn1;
        }

        pp ^= 1;
    }

    // ---- output head: warp reductions over the 40-dim embedding ----
    float s00 = fmaf(h0, wo0, hn0 * wo0i);
    float s01 = fmaf(h0, wo1, hn0 * wo1i);
    float s10 = fmaf(h1, wo0, hn1 * wo0i);
    float s11 = fmaf(h1, wo1, hn1 * wo1i);
#pragma unroll
    for (int d = 16; d > 0; d >>= 1) {
        s00 += __shfl_xor_sync(FULL, s00, d);
        s01 += __shfl_xor_sync(FULL, s01, d);
        s10 += __shfl_xor_sync(FULL, s10, d);
        s11 += __shfl_xor_sync(FULL, s11, d);
    }
    if (lane == 0) {
        float2 o0; o0.x = s00 + b_out[0]; o0.y = s01 + b_out[1];
        float2 o1; o1.x = s10 + b_out[0]; o1.y = s11 + b_out[1];
        ((float2*)out)[t * B_DIM + b0]     = o0;
        ((float2*)out)[t * B_DIM + b0 + 1] = o1;
    }
}

extern "C" void kernel_launch(void* const* d_in, const int* in_sizes, int n_in,
                              void* d_out, int out_size) {
    (void)in_sizes; (void)n_in; (void)out_size;
    const float* inputs  = (const float*)d_in[0];
    const float* Wih_his = (const float*)d_in[1];
    const float* Whh_his = (const float*)d_in[2];
    const float* bih_his = (const float*)d_in[3];
    const float* bhh_his = (const float*)d_in[4];
    const float* Wih_int = (const float*)d_in[5];
    const float* Whh_int = (const float*)d_in[6];
    const float* bih_int = (const float*)d_in[7];
    const float* bhh_int = (const float*)d_in[8];
    const float* W_out   = (const float*)d_in[9];
    const float* b_out   = (const float*)d_in[10];
    float* out = (float*)d_out;

    traj_kernel<<<NW / WARPS_PB, THREADS>>>(
        inputs, Wih_his, Whh_his, bih_his, bhh_his,
        Wih_int, Whh_int, bih_int, bhh_int,
        W_out, b_out, out);
}

// round 10
// speedup vs baseline: 7.7878x; 2.7106x over previous
#include <cuda_runtime.h>
#include <cuda_fp16.h>
#include <cstdint>

#define T_DIM 256
#define B_DIM 128
#define N_DIM 4
#define L_WIN 64
// one warp = 8 sequences (same t, 8 adjacent b); 4096 warps; 128-thd blocks
#define NWARPS 4096

// ---------- fast activations (MUFU.TANH) ----------
__device__ __forceinline__ float tanh_a(float x) {
    float y;
    asm("tanh.approx.f32 %0, %1;" : "=f"(y) : "f"(x));
    return y;
}
__device__ __forceinline__ float sig_a(float x) {
    return fmaf(0.5f, tanh_a(0.5f * x), 0.5f);
}

// ---------- fp16 pack / split helpers ----------
__device__ __forceinline__ uint32_t packh2(__half lo, __half hi) {
    __half2 v; v.x = lo; v.y = hi;
    return *reinterpret_cast<uint32_t*>(&v);
}
// f = float(a) + float(b) + O(2^-22): a = main fp16, b = fp16 residual
__device__ __forceinline__ void splitf(float f, __half& a, __half& b) {
    a = __float2half_rn(f);
    b = __float2half_rn(f - __half2float(a));
}
// load W[row][col], W[row][col+1]; produce packed main pair and residual pair
__device__ __forceinline__ void wsplit2(const float* W, int ld, int row, int col,
                                        uint32_t& w1, uint32_t& w2) {
    float f0 = W[row * ld + col], f1 = W[row * ld + col + 1];
    __half a0 = __float2half_rn(f0), a1 = __float2half_rn(f1);
    __half r0 = __float2half_rn(f0 - __half2float(a0));
    __half r1 = __float2half_rn(f1 - __half2float(a1));
    w1 = packh2(a0, a1);
    w2 = packh2(r0, r1);
}

// ---------- tensor core ops ----------
__device__ __forceinline__ void mma16816(float* d, const uint32_t* a,
                                         uint32_t b0, uint32_t b1) {
    asm("mma.sync.aligned.m16n8k16.row.col.f32.f16.f16.f32 "
        "{%0,%1,%2,%3}, {%4,%5,%6,%7}, {%8,%9}, {%0,%1,%2,%3};"
        : "+f"(d[0]), "+f"(d[1]), "+f"(d[2]), "+f"(d[3])
        : "r"(a[0]), "r"(a[1]), "r"(a[2]), "r"(a[3]), "r"(b0), "r"(b1));
}
__device__ __forceinline__ uint32_t movm(uint32_t s) {
    uint32_t d;
    asm("movmatrix.sync.aligned.m8n8.trans.b16 %0, %1;" : "=r"(d) : "r"(s));
    return d;
}

// Fragment conventions (m16n8k16, row.col):
//   A: lane(g=l>>2, tid=l&3): a0=(r=g, c=2tid,+1) a1=(g+8, same) a2=(g, +8) a3=(g+8, +8)
//   B: b0=(k=2tid,+1; n=g)  b1=(k=2tid+8,+9; n=g)
//   C: c0,c1=(row g, col 2tid,2tid+1)  c2,c3=(row g+8, same cols)
// gates G[128 rows x 8 seqs] = W[128x32] @ h[32x8]  (+ x/bias k-tile)
__global__ void __launch_bounds__(128) traj_kernel(
    const float* __restrict__ inputs,
    const float* __restrict__ Wih_his, const float* __restrict__ Whh_his,
    const float* __restrict__ bih_his, const float* __restrict__ bhh_his,
    const float* __restrict__ Wih_int, const float* __restrict__ Whh_int,
    const float* __restrict__ bih_int, const float* __restrict__ bhh_int,
    const float* __restrict__ W_out, const float* __restrict__ b_out,
    float* __restrict__ out)
{
    const unsigned FULL = 0xffffffffu;
    const int lane = threadIdx.x & 31;
    const int w = threadIdx.x >> 5;
    const int gw = blockIdx.x * 4 + w;
    const int t = (T_DIM - 1) - (gw >> 4);     // long windows first
    const int b0 = (gw & 15) * 8;
    const int g = lane >> 2, tid = lane & 3;
    const __half ONE = __float2half_rn(1.0f);

    // ---- his Whh A-frags: W1 (main) and W2 (residual) ----
    uint32_t A1[8][2][4], A2[8][2][4];
#pragma unroll
    for (int mt = 0; mt < 8; mt++) {
#pragma unroll
        for (int kt = 0; kt < 2; kt++) {
            int r0 = 16 * mt + g, r1 = r0 + 8;
            int c0 = 16 * kt + 2 * tid;
            wsplit2(Whh_his, 32, r0, c0,     A1[mt][kt][0], A2[mt][kt][0]);
            wsplit2(Whh_his, 32, r1, c0,     A1[mt][kt][1], A2[mt][kt][1]);
            wsplit2(Whh_his, 32, r0, c0 + 8, A1[mt][kt][2], A2[mt][kt][2]);
            wsplit2(Whh_his, 32, r1, c0 + 8, A1[mt][kt][3], A2[mt][kt][3]);
        }
    }
    // ---- his x/bias k-tile A-frags (cols: wx0_1,wx0_1,wx1_1,wx1_1,b_1,wx0_2,wx1_2,b_2) ----
    uint32_t XA[8][2];
#pragma unroll
    for (int mt = 0; mt < 8; mt++) {
#pragma unroll
        for (int half = 0; half < 2; half++) {
            int rr = 16 * mt + g + 8 * half;
            __half wx0_1, wx0_2, wx1_1, wx1_2, bb_1, bb_2;
            splitf(Wih_his[rr * 2 + 0], wx0_1, wx0_2);
            splitf(Wih_his[rr * 2 + 1], wx1_1, wx1_2);
            splitf(bih_his[rr] + bhh_his[rr], bb_1, bb_2);
            XA[mt][half] = (tid == 0) ? packh2(wx0_1, wx0_1)
                         : (tid == 1) ? packh2(wx1_1, wx1_1)
                         : (tid == 2) ? packh2(bb_1, wx0_2)
                                      : packh2(wx1_2, bb_2);
        }
    }
    // ---- int A-frags: ik0 = [W1|W1] (a2=a0,a3=a1); ik1 = [W2 | xcols] ----
    uint32_t IA1[2][2], IA2[2][4];
#pragma unroll
    for (int mt = 0; mt < 2; mt++) {
#pragma unroll
        for (int half = 0; half < 2; half++) {
            int rr = 16 * mt + g + 8 * half;
            wsplit2(Whh_int, 8, rr, 2 * tid, IA1[mt][half], IA2[mt][half]);
            __half wx0_1, wx0_2, wx1_1, wx1_2, bb_1, bb_2;
            splitf(Wih_int[rr * 2 + 0], wx0_1, wx0_2);
            splitf(Wih_int[rr * 2 + 1], wx1_1, wx1_2);
            splitf(bih_int[rr] + bhh_int[rr], bb_1, bb_2);
            IA2[mt][2 + half] = (tid == 0) ? packh2(wx0_1, wx0_1)
                              : (tid == 1) ? packh2(wx1_1, wx1_1)
                              : (tid == 2) ? packh2(bb_1, wx0_2)
                                           : packh2(wx1_2, bb_2);
        }
    }

    // ---- recurrent state ----
    float cst[2][4], hst[2][4];
#pragma unroll
    for (int v = 0; v < 2; v++)
#pragma unroll
        for (int j = 0; j < 4; j++) { cst[v][j] = 0.0f; hst[v][j] = 0.0f; }
    float cint[2] = {0.0f, 0.0f}, hint[2] = {0.0f, 0.0f};
    uint32_t bh1[4] = {0, 0, 0, 0}, bh2[4] = {0, 0, 0, 0};
    uint32_t bih1 = 0, bih2 = 0;

    int a0 = t - (L_WIN - 1);
    if (a0 < 0) a0 = 0;

    const float2* __restrict__ inp2 = (const float2*)inputs; // [T,B,N] float2
    const long STRIDE = (long)B_DIM * N_DIM;
    long base = ((long)a0 * B_DIM + (b0 + g)) * N_DIM;  // lane loads seq g's x
    float2 xh = inp2[base + 3];   // node -1 (his)
    float2 xi = inp2[base + 0];   // node 0  (int)

    for (int a = a0; a <= t; a++) {
        // prefetch next step
        float2 xhn = xh, xin = xi;
        if (a < t) { xhn = inp2[base + STRIDE + 3]; xin = inp2[base + STRIDE + 0]; }
        base += STRIDE;

        // x B-frags (k rows: x0h,x0l,x1h,x1l,1,x0h,x1h,1)
        __half x0h, x0l, x1h, x1l;
        splitf(xh.x, x0h, x0l); splitf(xh.y, x1h, x1l);
        uint32_t bx = (tid == 0) ? packh2(x0h, x0l)
                    : (tid == 1) ? packh2(x1h, x1l)
                    : (tid == 2) ? packh2(ONE, x0h)
                                 : packh2(x1h, ONE);
        splitf(xi.x, x0h, x0l); splitf(xi.y, x1h, x1l);
        uint32_t bxi = (tid == 0) ? packh2(x0h, x0l)
                     : (tid == 1) ? packh2(x1h, x1l)
                     : (tid == 2) ? packh2(ONE, x0h)
                                  : packh2(x1h, ONE);

        // --- his gates: 7 MMAs per 16-row tile ---
        float d[8][4];
#pragma unroll
        for (int mt = 0; mt < 8; mt++) {
            d[mt][0] = d[mt][1] = d[mt][2] = d[mt][3] = 0.0f;
            mma16816(d[mt], A1[mt][0], bh1[0], bh1[1]);   // W1 @ h1 (k 0-15)
            mma16816(d[mt], A1[mt][1], bh1[2], bh1[3]);   // W1 @ h1 (k 16-31)
            mma16816(d[mt], A1[mt][0], bh2[0], bh2[1]);   // W1 @ h2
            mma16816(d[mt], A1[mt][1], bh2[2], bh2[3]);
            mma16816(d[mt], A2[mt][0], bh1[0], bh1[1]);   // W2 @ h1
            mma16816(d[mt], A2[mt][1], bh1[2], bh1[3]);
            uint32_t xa[4] = {XA[mt][0], XA[mt][1], 0u, 0u};
            mma16816(d[mt], xa, bx, 0u);                  // x + bias
        }
        // --- int gates: 2 MMAs per tile ---
        float di[2][4];
#pragma unroll
        for (int mt = 0; mt < 2; mt++) {
            di[mt][0] = di[mt][1] = di[mt][2] = di[mt][3] = 0.0f;
            uint32_t a_[4] = {IA1[mt][0], IA1[mt][1], IA1[mt][0], IA1[mt][1]};
            mma16816(di[mt], a_, bih1, bih2);             // W1@h1 + W1@h2
            mma16816(di[mt], IA2[mt], bih1, bxi);         // W2@h1 + x + bias
        }

        // --- his activations & state update ---
        __half h1h[2][4], h2h[2][4];
#pragma unroll
        for (int v = 0; v < 2; v++) {
#pragma unroll
            for (int j = 0; j < 4; j++) {
                float si = sig_a(d[0 + v][j]);
                float sf = sig_a(d[2 + v][j]);
                float tg = tanh_a(d[4 + v][j]);
                float so = sig_a(d[6 + v][j]);
                float c = fmaf(sf, cst[v][j], si * tg);
                cst[v][j] = c;
                float h = so * tanh_a(c);
                hst[v][j] = h;
                splitf(h, h1h[v][j], h2h[v][j]);
            }
        }
        // D-layout -> B-layout via movmatrix (8x8 b16 transpose)
        bh1[0] = movm(packh2(h1h[0][0], h1h[0][1]));  // units 0-7
        bh1[1] = movm(packh2(h1h[0][2], h1h[0][3]));  // units 8-15
        bh1[2] = movm(packh2(h1h[1][0], h1h[1][1]));  // units 16-23
        bh1[3] = movm(packh2(h1h[1][2], h1h[1][3]));  // units 24-31
        bh2[0] = movm(packh2(h2h[0][0], h2h[0][1]));
        bh2[1] = movm(packh2(h2h[0][2], h2h[0][3]));
        bh2[2] = movm(packh2(h2h[1][0], h2h[1][1]));
        bh2[3] = movm(packh2(h2h[1][2], h2h[1][3]));

        // --- int activations ---
#pragma unroll
        for (int j = 0; j < 2; j++) {
            float si = sig_a(di[0][j]);
            float sf = sig_a(di[0][2 + j]);
            float tg = tanh_a(di[1][j]);
            float so = sig_a(di[1][2 + j]);
            float c = fmaf(sf, cint[j], si * tg);
            cint[j] = c;
            hint[j] = so * tanh_a(c);
        }
        {
            __half i1a, i2a, i1b, i2b;
            splitf(hint[0], i1a, i2a);
            splitf(hint[1], i1b, i2b);
            bih1 = movm(packh2(i1a, i1b));
            bih2 = movm(packh2(i2a, i2b));
        }

        xh = xhn; xi = xin;
    }

    // ---- output head ----
    // lane holds h for units {16v + g + 8*(j>>1)}, seq cols {2tid + (j&1)}
    float p00 = 0.0f, p01 = 0.0f, p10 = 0.0f, p11 = 0.0f;
#pragma unroll
    for (int v = 0; v < 2; v++) {
#pragma unroll
        for (int j = 0; j < 4; j++) {
            int unit = 16 * v + g + 8 * (j >> 1);
            float wo0 = W_out[unit], wo1 = W_out[40 + unit];
            if ((j & 1) == 0) { p00 = fmaf(hst[v][j], wo0, p00); p01 = fmaf(hst[v][j], wo1, p01); }
            else              { p10 = fmaf(hst[v][j], wo0, p10); p11 = fmaf(hst[v][j], wo1, p11); }
        }
    }
    {   // int part: lane holds h_int[unit g] for seqs 2tid, 2tid+1
        float wi0 = W_out[32 + g], wi1 = W_out[72 + g];
        p00 = fmaf(hint[0], wi0, p00); p01 = fmaf(hint[0], wi1, p01);
        p10 = fmaf(hint[1], wi0, p10); p11 = fmaf(hint[1], wi1, p11);
    }
    // reduce across g (lane bits 2-4)
#pragma unroll
    for (int m = 4; m <= 16; m <<= 1) {
        p00 += __shfl_xor_sync(FULL, p00, m);
        p01 += __shfl_xor_sync(FULL, p01, m);
        p10 += __shfl_xor_sync(FULL, p10, m);
        p11 += __shfl_xor_sync(FULL, p11, m);
    }
    if (g == 0) {   // lanes 0-3: tid covers seq pairs (2tid, 2tid+1)
        float4 o;
        o.x = p00 + b_out[0]; o.y = p01 + b_out[1];
        o.z = p10 + b_out[0]; o.w = p11 + b_out[1];
        ((float4*)out)[(t * B_DIM + b0) / 2 + tid] = o;
    }
}

extern "C" void kernel_launch(void* const* d_in, const int* in_sizes, int n_in,
                              void* d_out, int out_size) {
    (void)in_sizes; (void)n_in; (void)out_size;
    const float* inputs  = (const float*)d_in[0];
    const float* Wih_his = (const float*)d_in[1];
    const float* Whh_his = (const float*)d_in[2];
    const float* bih_his = (const float*)d_in[3];
    const float* bhh_his = (const float*)d_in[4];
    const float* Wih_int = (const float*)d_in[5];
    const float* Whh_int = (const float*)d_in[6];
    const float* bih_int = (const float*)d_in[7];
    const float* bhh_int = (const float*)d_in[8];
    const float* W_out   = (const float*)d_in[9];
    const float* b_out   = (const float*)d_in[10];
    float* out = (float*)d_out;

    // 4096 warps (8 seqs each) in 1024 blocks of 128 threads
    traj_kernel<<<NWARPS / 4, 128>>>(inputs, Wih_his, Whh_his, bih_his, bhh_his,
                                     Wih_int, Whh_int, bih_int, bhh_int,
                                     W_out, b_out, out);
}

// round 12
// speedup vs baseline: 8.6529x; 1.1111x over previous
#include <cuda_runtime.h>
#include <cuda_fp16.h>
#include <cstdint>

#define T_DIM 256
#define B_DIM 128
#define N_DIM 4
#define L_WIN 64
// one warp = 8 sequences (same t, 8 adjacent b); 4096 warps; 128-thd blocks
#define NWARPS 4096

// ---------- fast activations (MUFU.TANH, fp32 in/out) ----------
__device__ __forceinline__ float tanh_a(float x) {
    float y;
    asm("tanh.approx.f32 %0, %1;" : "=f"(y) : "f"(x));
    return y;
}
__device__ __forceinline__ float sig_a(float x) {
    return fmaf(0.5f, tanh_a(0.5f * x), 0.5f);
}

// ---------- fp16 pack / split helpers ----------
__device__ __forceinline__ uint32_t packh2(__half lo, __half hi) {
    __half2 v; v.x = lo; v.y = hi;
    return *reinterpret_cast<uint32_t*>(&v);
}
// f = float(a) + float(b) + O(2^-22)
__device__ __forceinline__ void splitf(float f, __half& a, __half& b) {
    a = __float2half_rn(f);
    b = __float2half_rn(f - __half2float(a));
}
__device__ __forceinline__ void wsplit2(const float* W, int ld, int row, int col,
                                        uint32_t& w1, uint32_t& w2) {
    float f0 = W[row * ld + col], f1 = W[row * ld + col + 1];
    __half a0 = __float2half_rn(f0), a1 = __float2half_rn(f1);
    __half r0 = __float2half_rn(f0 - __half2float(a0));
    __half r1 = __float2half_rn(f1 - __half2float(a1));
    w1 = packh2(a0, a1);
    w2 = packh2(r0, r1);
}

// ---------- tensor core ops ----------
__device__ __forceinline__ void mma16816(float* d, const uint32_t* a,
                                         uint32_t b0, uint32_t b1) {
    asm("mma.sync.aligned.m16n8k16.row.col.f32.f16.f16.f32 "
        "{%0,%1,%2,%3}, {%4,%5,%6,%7}, {%8,%9}, {%0,%1,%2,%3};"
        : "+f"(d[0]), "+f"(d[1]), "+f"(d[2]), "+f"(d[3])
        : "r"(a[0]), "r"(a[1]), "r"(a[2]), "r"(a[3]), "r"(b0), "r"(b1));
}
__device__ __forceinline__ uint32_t movm(uint32_t s) {
    uint32_t d;
    asm("movmatrix.sync.aligned.m8n8.trans.b16 %0, %1;" : "=r"(d) : "r"(s));
    return d;
}

// Fragment conventions (m16n8k16, row.col):
//   A: lane(g=l>>2, tid=l&3): a0=(r=g, c=2tid,+1) a1=(g+8, same) a2=(g, +8) a3=(g+8, +8)
//   B: b0=(k=2tid,+1; n=g)  b1=(k=2tid+8,+9; n=g)
//   C: c0,c1=(row g, col 2tid,2tid+1)  c2,c3=(row g+8, same cols)
// h recirculates as EXACT fp16 (quantized after the fp32 cell update), so
// gates = W1@h + W2@h + x-tile (weight residual exact, no h residual term).
// Activations and c remain fp32; output head uses pre-quantization fp32 h.
__global__ void __launch_bounds__(128) traj_kernel(
    const float* __restrict__ inputs,
    const float* __restrict__ Wih_his, const float* __restrict__ Whh_his,
    const float* __restrict__ bih_his, const float* __restrict__ bhh_his,
    const float* __restrict__ Wih_int, const float* __restrict__ Whh_int,
    const float* __restrict__ bih_int, const float* __restrict__ bhh_int,
    const float* __restrict__ W_out, const float* __restrict__ b_out,
    float* __restrict__ out)
{
    const unsigned FULL = 0xffffffffu;
    const int lane = threadIdx.x & 31;
    const int w = threadIdx.x >> 5;
    const int gw = blockIdx.x * 4 + w;
    const int t = (T_DIM - 1) - (gw >> 4);     // long windows first
    const int b0 = (gw & 15) * 8;
    const int g = lane >> 2, tid = lane & 3;
    const __half ONE = __float2half_rn(1.0f);

    // ---- his Whh A-frags: W1 (main) and W2 (residual) ----
    uint32_t A1[8][2][4], A2[8][2][4];
#pragma unroll
    for (int mt = 0; mt < 8; mt++) {
#pragma unroll
        for (int kt = 0; kt < 2; kt++) {
            int r0 = 16 * mt + g, r1 = r0 + 8;
            int c0 = 16 * kt + 2 * tid;
            wsplit2(Whh_his, 32, r0, c0,     A1[mt][kt][0], A2[mt][kt][0]);
            wsplit2(Whh_his, 32, r1, c0,     A1[mt][kt][1], A2[mt][kt][1]);
            wsplit2(Whh_his, 32, r0, c0 + 8, A1[mt][kt][2], A2[mt][kt][2]);
            wsplit2(Whh_his, 32, r1, c0 + 8, A1[mt][kt][3], A2[mt][kt][3]);
        }
    }
    // ---- his x/bias k-tile A-frags (cols: wx0_1,wx0_1,wx1_1,wx1_1,b_1,wx0_2,wx1_2,b_2) ----
    uint32_t XA[8][2];
#pragma unroll
    for (int mt = 0; mt < 8; mt++) {
#pragma unroll
        for (int half = 0; half < 2; half++) {
            int rr = 16 * mt + g + 8 * half;
            __half wx0_1, wx0_2, wx1_1, wx1_2, bb_1, bb_2;
            splitf(Wih_his[rr * 2 + 0], wx0_1, wx0_2);
            splitf(Wih_his[rr * 2 + 1], wx1_1, wx1_2);
            splitf(bih_his[rr] + bhh_his[rr], bb_1, bb_2);
            XA[mt][half] = (tid == 0) ? packh2(wx0_1, wx0_1)
                         : (tid == 1) ? packh2(wx1_1, wx1_1)
                         : (tid == 2) ? packh2(bb_1, wx0_2)
                                      : packh2(wx1_2, bb_2);
        }
    }
    // ---- int A-frags: MMA1 = [W1 | W2] @ [h; h]; MMA2 = x/bias tile ----
    uint32_t IA1[2][2], IAW2[2][2], IAX[2][2];
#pragma unroll
    for (int mt = 0; mt < 2; mt++) {
#pragma unroll
        for (int half = 0; half < 2; half++) {
            int rr = 16 * mt + g + 8 * half;
            wsplit2(Whh_int, 8, rr, 2 * tid, IA1[mt][half], IAW2[mt][half]);
            __half wx0_1, wx0_2, wx1_1, wx1_2, bb_1, bb_2;
            splitf(Wih_int[rr * 2 + 0], wx0_1, wx0_2);
            splitf(Wih_int[rr * 2 + 1], wx1_1, wx1_2);
            splitf(bih_int[rr] + bhh_int[rr], bb_1, bb_2);
            IAX[mt][half] = (tid == 0) ? packh2(wx0_1, wx0_1)
                          : (tid == 1) ? packh2(wx1_1, wx1_1)
                          : (tid == 2) ? packh2(bb_1, wx0_2)
                                       : packh2(wx1_2, bb_2);
        }
    }

    // ---- recurrent state ----
    float cst[2][4], hst[2][4];
#pragma unroll
    for (int v = 0; v < 2; v++)
#pragma unroll
        for (int j = 0; j < 4; j++) { cst[v][j] = 0.0f; hst[v][j] = 0.0f; }
    float cint[2] = {0.0f, 0.0f}, hint[2] = {0.0f, 0.0f};
    uint32_t bh1[4] = {0, 0, 0, 0};
    uint32_t bih1 = 0;

    int a0 = t - (L_WIN - 1);
    if (a0 < 0) a0 = 0;

    const float2* __restrict__ inp2 = (const float2*)inputs; // [T,B,N] float2
    const long STRIDE = (long)B_DIM * N_DIM;
    long base = ((long)a0 * B_DIM + (b0 + g)) * N_DIM;  // lane loads seq g's x
    float2 xh = inp2[base + 3];   // node -1 (his)
    float2 xi = inp2[base + 0];   // node 0  (int)

    for (int a = a0; a <= t; a++) {
        // prefetch next step
        float2 xhn = xh, xin = xi;
        if (a < t) { xhn = inp2[base + STRIDE + 3]; xin = inp2[base + STRIDE + 0]; }
        base += STRIDE;

        // x B-frags (k rows: x0h,x0l,x1h,x1l,1,x0h,x1h,1)
        __half x0h, x0l, x1h, x1l;
        splitf(xh.x, x0h, x0l); splitf(xh.y, x1h, x1l);
        uint32_t bx = (tid == 0) ? packh2(x0h, x0l)
                    : (tid == 1) ? packh2(x1h, x1l)
                    : (tid == 2) ? packh2(ONE, x0h)
                                 : packh2(x1h, ONE);
        splitf(xi.x, x0h, x0l); splitf(xi.y, x1h, x1l);
        uint32_t bxi = (tid == 0) ? packh2(x0h, x0l)
                     : (tid == 1) ? packh2(x1h, x1l)
                     : (tid == 2) ? packh2(ONE, x0h)
                                  : packh2(x1h, ONE);

        // --- his gates: 5 MMAs per 16-row tile (h has no residual) ---
        float d[8][4];
#pragma unroll
        for (int mt = 0; mt < 8; mt++) {
            d[mt][0] = d[mt][1] = d[mt][2] = d[mt][3] = 0.0f;
            mma16816(d[mt], A1[mt][0], bh1[0], bh1[1]);   // W1 @ h (k 0-15)
            mma16816(d[mt], A1[mt][1], bh1[2], bh1[3]);   // W1 @ h (k 16-31)
            mma16816(d[mt], A2[mt][0], bh1[0], bh1[1]);   // W2 @ h (k 0-15)
            mma16816(d[mt], A2[mt][1], bh1[2], bh1[3]);   // W2 @ h (k 16-31)
            uint32_t xa[4] = {XA[mt][0], XA[mt][1], 0u, 0u};
            mma16816(d[mt], xa, bx, 0u);                  // x + bias
        }
        // --- int gates: 2 MMAs per tile ---
        float di[2][4];
#pragma unroll
        for (int mt = 0; mt < 2; mt++) {
            di[mt][0] = di[mt][1] = di[mt][2] = di[mt][3] = 0.0f;
            uint32_t a1_[4] = {IA1[mt][0], IA1[mt][1], IAW2[mt][0], IAW2[mt][1]};
            mma16816(di[mt], a1_, bih1, bih1);            // (W1 + W2) @ h
            uint32_t a2_[4] = {IAX[mt][0], IAX[mt][1], 0u, 0u};
            mma16816(di[mt], a2_, bxi, 0u);               // x + bias
        }

        // --- his activations (fp32) & state update; h -> exact fp16 ---
        __half h16[2][4];
#pragma unroll
        for (int v = 0; v < 2; v++) {
#pragma unroll
            for (int j = 0; j < 4; j++) {
                float si = sig_a(d[0 + v][j]);
                float sf = sig_a(d[2 + v][j]);
                float tg = tanh_a(d[4 + v][j]);
                float so = sig_a(d[6 + v][j]);
                float c = fmaf(sf, cst[v][j], si * tg);
                cst[v][j] = c;
                float h = so * tanh_a(c);
                hst[v][j] = h;                       // fp32 copy for output head
                h16[v][j] = __float2half_rn(h);      // recirculated value
            }
        }
        // D-layout -> B-layout via movmatrix (8x8 b16 transpose)
        bh1[0] = movm(packh2(h16[0][0], h16[0][1]));  // units 0-7
        bh1[1] = movm(packh2(h16[0][2], h16[0][3]));  // units 8-15
        bh1[2] = movm(packh2(h16[1][0], h16[1][1]));  // units 16-23
        bh1[3] = movm(packh2(h16[1][2], h16[1][3]));  // units 24-31

        // --- int activations ---
#pragma unroll
        for (int j = 0; j < 2; j++) {
            float si = sig_a(di[0][j]);
            float sf = sig_a(di[0][2 + j]);
            float tg = tanh_a(di[1][j]);
            float so = sig_a(di[1][2 + j]);
            float c = fmaf(sf, cint[j], si * tg);
            cint[j] = c;
            hint[j] = so * tanh_a(c);
        }
        bih1 = movm(packh2(__float2half_rn(hint[0]), __float2half_rn(hint[1])));

        xh = xhn; xi = xin;
    }

    // ---- output head (uses fp32 h) ----
    // lane holds h for units {16v + g + 8*(j>>1)}, seq cols {2tid + (j&1)}
    float p00 = 0.0f, p01 = 0.0f, p10 = 0.0f, p11 = 0.0f;
#pragma unroll
    for (int v = 0; v < 2; v++) {
#pragma unroll
        for (int j = 0; j < 4; j++) {
            int unit = 16 * v + g + 8 * (j >> 1);
            float wo0 = W_out[unit], wo1 = W_out[40 + unit];
            if ((j & 1) == 0) { p00 = fmaf(hst[v][j], wo0, p00); p01 = fmaf(hst[v][j], wo1, p01); }
            else              { p10 = fmaf(hst[v][j], wo0, p10); p11 = fmaf(hst[v][j], wo1, p11); }
        }
    }
    {   // int part: lane holds h_int[unit g] for seqs 2tid, 2tid+1
        float wi0 = W_out[32 + g], wi1 = W_out[72 + g];
        p00 = fmaf(hint[0], wi0, p00); p01 = fmaf(hint[0], wi1, p01);
        p10 = fmaf(hint[1], wi0, p10); p11 = fmaf(hint[1], wi1, p11);
    }
    // reduce across g (lane bits 2-4)
#pragma unroll
    for (int m = 4; m <= 16; m <<= 1) {
        p00 += __shfl_xor_sync(FULL, p00, m);
        p01 += __shfl_xor_sync(FULL, p01, m);
        p10 += __shfl_xor_sync(FULL, p10, m);
        p11 += __shfl_xor_sync(FULL, p11, m);
    }
    if (g == 0) {   // lanes 0-3: tid covers seq pairs (2tid, 2tid+1)
        float4 o;
        o.x = p00 + b_out[0]; o.y = p01 + b_out[1];
        o.z = p10 + b_out[0]; o.w = p11 + b_out[1];
        ((float4*)out)[(t * B_DIM + b0) / 2 + tid] = o;
    }
}

extern "C" void kernel_launch(void* const* d_in, const int* in_sizes, int n_in,
                              void* d_out, int out_size) {
    (void)in_sizes; (void)n_in; (void)out_size;
    const float* inputs  = (const float*)d_in[0];
    const float* Wih_his = (const float*)d_in[1];
    const float* Whh_his = (const float*)d_in[2];
    const float* bih_his = (const float*)d_in[3];
    const float* bhh_his = (const float*)d_in[4];
    const float* Wih_int = (const float*)d_in[5];
    const float* Whh_int = (const float*)d_in[6];
    const float* bih_int = (const float*)d_in[7];
    const float* bhh_int = (const float*)d_in[8];
    const float* W_out   = (const float*)d_in[9];
    const float* b_out   = (const float*)d_in[10];
    float* out = (float*)d_out;

    // 4096 warps (8 seqs each) in 1024 blocks of 128 threads
    traj_kernel<<<NWARPS / 4, 128>>>(inputs, Wih_his, Whh_his, bih_his, bhh_his,
                                     Wih_int, Whh_int, bih_int, bhh_int,
                                     W_out, b_out, out);
}

// round 13
// speedup vs baseline: 9.8832x; 1.1422x over previous
#include <cuda_runtime.h>
#include <cuda_fp16.h>
#include <cstdint>

#define T_DIM 256
#define B_DIM 128
#define N_DIM 4
#define L_WIN 64
// one warp = 8 sequences (same t, 8 adjacent b); 4096 single-warp blocks
#define NWARPS 4096

// ---------- fast activations (MUFU.TANH, fp32 in/out) ----------
__device__ __forceinline__ float tanh_a(float x) {
    float y;
    asm("tanh.approx.f32 %0, %1;" : "=f"(y) : "f"(x));
    return y;
}
__device__ __forceinline__ float sig_a(float x) {
    return fmaf(0.5f, tanh_a(0.5f * x), 0.5f);
}

// ---------- fp16 pack / split helpers ----------
__device__ __forceinline__ uint32_t packh2(__half lo, __half hi) {
    __half2 v; v.x = lo; v.y = hi;
    return *reinterpret_cast<uint32_t*>(&v);
}
__device__ __forceinline__ void splitf(float f, __half& a, __half& b) {
    a = __float2half_rn(f);
    b = __float2half_rn(f - __half2float(a));
}
// plain fp16 weight pair (no residual tracking)
__device__ __forceinline__ uint32_t wpack2(const float* W, int ld, int row, int col) {
    return packh2(__float2half_rn(W[row * ld + col]),
                  __float2half_rn(W[row * ld + col + 1]));
}

// ---------- tensor core ops ----------
__device__ __forceinline__ void mma16816(float* d, const uint32_t* a,
                                         uint32_t b0, uint32_t b1) {
    asm("mma.sync.aligned.m16n8k16.row.col.f32.f16.f16.f32 "
        "{%0,%1,%2,%3}, {%4,%5,%6,%7}, {%8,%9}, {%0,%1,%2,%3};"
        : "+f"(d[0]), "+f"(d[1]), "+f"(d[2]), "+f"(d[3])
        : "r"(a[0]), "r"(a[1]), "r"(a[2]), "r"(a[3]), "r"(b0), "r"(b1));
}
__device__ __forceinline__ uint32_t movm(uint32_t s) {
    uint32_t d;
    asm("movmatrix.sync.aligned.m8n8.trans.b16 %0, %1;" : "=r"(d) : "r"(s));
    return d;
}

// Fragment conventions (m16n8k16, row.col):
//   A: lane(g=l>>2, tid=l&3): a0=(r=g, c=2tid,+1) a1=(g+8, same) a2=(g, +8) a3=(g+8, +8)
//   B: b0=(k=2tid,+1; n=g)  b1=(k=2tid+8,+9; n=g)
//   C: c0,c1=(row g, col 2tid,2tid+1)  c2,c3=(row g+8, same cols)
// Weights in plain fp16 (no residual): h-quantization (fp16 recirculation)
// already bounds accuracy at ~2^-11; measured margin is >10x the 1e-3 gate.
// x/bias keep split-fp16 columns (cheap, same MMA). c and activations fp32.
__global__ void __launch_bounds__(32) traj_kernel(
    const float* __restrict__ inputs,
    const float* __restrict__ Wih_his, const float* __restrict__ Whh_his,
    const float* __restrict__ bih_his, const float* __restrict__ bhh_his,
    const float* __restrict__ Wih_int, const float* __restrict__ Whh_int,
    const float* __restrict__ bih_int, const float* __restrict__ bhh_int,
    const float* __restrict__ W_out, const float* __restrict__ b_out,
    float* __restrict__ out)
{
    const unsigned FULL = 0xffffffffu;
    const int lane = threadIdx.x;
    const int gw = blockIdx.x;
    const int t = (T_DIM - 1) - (gw >> 4);     // long windows first
    const int b0 = (gw & 15) * 8;
    const int g = lane >> 2, tid = lane & 3;
    const __half ONE = __float2half_rn(1.0f);

    // ---- his Whh A-frags (fp16 main only) ----
    uint32_t A1[8][2][4];
#pragma unroll
    for (int mt = 0; mt < 8; mt++) {
#pragma unroll
        for (int kt = 0; kt < 2; kt++) {
            int r0 = 16 * mt + g, r1 = r0 + 8;
            int c0 = 16 * kt + 2 * tid;
            A1[mt][kt][0] = wpack2(Whh_his, 32, r0, c0);
            A1[mt][kt][1] = wpack2(Whh_his, 32, r1, c0);
            A1[mt][kt][2] = wpack2(Whh_his, 32, r0, c0 + 8);
            A1[mt][kt][3] = wpack2(Whh_his, 32, r1, c0 + 8);
        }
    }
    // ---- his x/bias k-tile A-frags (split-fp16 x/bias columns) ----
    uint32_t XA[8][2];
#pragma unroll
    for (int mt = 0; mt < 8; mt++) {
#pragma unroll
        for (int half = 0; half < 2; half++) {
            int rr = 16 * mt + g + 8 * half;
            __half wx0_1, wx0_2, wx1_1, wx1_2, bb_1, bb_2;
            splitf(Wih_his[rr * 2 + 0], wx0_1, wx0_2);
            splitf(Wih_his[rr * 2 + 1], wx1_1, wx1_2);
            splitf(bih_his[rr] + bhh_his[rr], bb_1, bb_2);
            XA[mt][half] = (tid == 0) ? packh2(wx0_1, wx0_1)
                         : (tid == 1) ? packh2(wx1_1, wx1_1)
                         : (tid == 2) ? packh2(bb_1, wx0_2)
                                      : packh2(wx1_2, bb_2);
        }
    }
    // ---- int A-frags ----
    uint32_t IA1[2][2], IAX[2][2];
#pragma unroll
    for (int mt = 0; mt < 2; mt++) {
#pragma unroll
        for (int half = 0; half < 2; half++) {
            int rr = 16 * mt + g + 8 * half;
            IA1[mt][half] = wpack2(Whh_int, 8, rr, 2 * tid);
            __half wx0_1, wx0_2, wx1_1, wx1_2, bb_1, bb_2;
            splitf(Wih_int[rr * 2 + 0], wx0_1, wx0_2);
            splitf(Wih_int[rr * 2 + 1], wx1_1, wx1_2);
            splitf(bih_int[rr] + bhh_int[rr], bb_1, bb_2);
            IAX[mt][half] = (tid == 0) ? packh2(wx0_1, wx0_1)
                          : (tid == 1) ? packh2(wx1_1, wx1_1)
                          : (tid == 2) ? packh2(bb_1, wx0_2)
                                       : packh2(wx1_2, bb_2);
        }
    }

    // ---- recurrent state ----
    float cst[2][4], hst[2][4];
#pragma unroll
    for (int v = 0; v < 2; v++)
#pragma unroll
        for (int j = 0; j < 4; j++) { cst[v][j] = 0.0f; hst[v][j] = 0.0f; }
    float cint[2] = {0.0f, 0.0f}, hint[2] = {0.0f, 0.0f};
    uint32_t bh1[4] = {0, 0, 0, 0};
    uint32_t bih1 = 0;

    int a0 = t - (L_WIN - 1);
    if (a0 < 0) a0 = 0;

    const float2* __restrict__ inp2 = (const float2*)inputs; // [T,B,N] float2
    const long STRIDE = (long)B_DIM * N_DIM;
    long base = ((long)a0 * B_DIM + (b0 + g)) * N_DIM;  // lane loads seq g's x
    float2 xh = inp2[base + 3];   // node -1 (his)
    float2 xi = inp2[base + 0];   // node 0  (int)

    for (int a = a0; a <= t; a++) {
        // prefetch next step
        float2 xhn = xh, xin = xi;
        if (a < t) { xhn = inp2[base + STRIDE + 3]; xin = inp2[base + STRIDE + 0]; }
        base += STRIDE;

        // x B-frags (k rows: x0h,x0l,x1h,x1l,1,x0h,x1h,1)
        __half x0h, x0l, x1h, x1l;
        splitf(xh.x, x0h, x0l); splitf(xh.y, x1h, x1l);
        uint32_t bx = (tid == 0) ? packh2(x0h, x0l)
                    : (tid == 1) ? packh2(x1h, x1l)
                    : (tid == 2) ? packh2(ONE, x0h)
                                 : packh2(x1h, ONE);
        splitf(xi.x, x0h, x0l); splitf(xi.y, x1h, x1l);
        uint32_t bxi = (tid == 0) ? packh2(x0h, x0l)
                     : (tid == 1) ? packh2(x1h, x1l)
                     : (tid == 2) ? packh2(ONE, x0h)
                                  : packh2(x1h, ONE);

        // --- his gates: 3 MMAs per 16-row tile ---
        float d[8][4];
#pragma unroll
        for (int mt = 0; mt < 8; mt++) {
            d[mt][0] = d[mt][1] = d[mt][2] = d[mt][3] = 0.0f;
            mma16816(d[mt], A1[mt][0], bh1[0], bh1[1]);   // W @ h (k 0-15)
            mma16816(d[mt], A1[mt][1], bh1[2], bh1[3]);   // W @ h (k 16-31)
            uint32_t xa[4] = {XA[mt][0], XA[mt][1], 0u, 0u};
            mma16816(d[mt], xa, bx, 0u);                  // x + bias
        }
        // --- int gates: 2 MMAs per tile ---
        float di[2][4];
#pragma unroll
        for (int mt = 0; mt < 2; mt++) {
            di[mt][0] = di[mt][1] = di[mt][2] = di[mt][3] = 0.0f;
            uint32_t a1_[4] = {IA1[mt][0], IA1[mt][1], 0u, 0u};
            mma16816(di[mt], a1_, bih1, 0u);              // W @ h (k 0-7 live)
            uint32_t a2_[4] = {IAX[mt][0], IAX[mt][1], 0u, 0u};
            mma16816(di[mt], a2_, bxi, 0u);               // x + bias
        }

        // --- his activations (fp32) & state update; h -> exact fp16 ---
        __half h16[2][4];
#pragma unroll
        for (int v = 0; v < 2; v++) {
#pragma unroll
            for (int j = 0; j < 4; j++) {
                float si = sig_a(d[0 + v][j]);
                float sf = sig_a(d[2 + v][j]);
                float tg = tanh_a(d[4 + v][j]);
                float so = sig_a(d[6 + v][j]);
                float c = fmaf(sf, cst[v][j], si * tg);
                cst[v][j] = c;
                float h = so * tanh_a(c);
                hst[v][j] = h;                       // fp32 copy for output head
                h16[v][j] = __float2half_rn(h);      // recirculated value
            }
        }
        // D-layout -> B-layout via movmatrix (8x8 b16 transpose)
        bh1[0] = movm(packh2(h16[0][0], h16[0][1]));  // units 0-7
        bh1[1] = movm(packh2(h16[0][2], h16[0][3]));  // units 8-15
        bh1[2] = movm(packh2(h16[1][0], h16[1][1]));  // units 16-23
        bh1[3] = movm(packh2(h16[1][2], h16[1][3]));  // units 24-31

        // --- int activations ---
#pragma unroll
        for (int j = 0; j < 2; j++) {
            float si = sig_a(di[0][j]);
            float sf = sig_a(di[0][2 + j]);
            float tg = tanh_a(di[1][j]);
            float so = sig_a(di[1][2 + j]);
            float c = fmaf(sf, cint[j], si * tg);
            cint[j] = c;
            hint[j] = so * tanh_a(c);
        }
        bih1 = movm(packh2(__float2half_rn(hint[0]), __float2half_rn(hint[1])));

        xh = xhn; xi = xin;
    }

    // ---- output head (uses fp32 h) ----
    float p00 = 0.0f, p01 = 0.0f, p10 = 0.0f, p11 = 0.0f;
#pragma unroll
    for (int v = 0; v < 2; v++) {
#pragma unroll
        for (int j = 0; j < 4; j++) {
            int unit = 16 * v + g + 8 * (j >> 1);
            float wo0 = W_out[unit], wo1 = W_out[40 + unit];
            if ((j & 1) == 0) { p00 = fmaf(hst[v][j], wo0, p00); p01 = fmaf(hst[v][j], wo1, p01); }
            else              { p10 = fmaf(hst[v][j], wo0, p10); p11 = fmaf(hst[v][j], wo1, p11); }
        }
    }
    {   // int part: lane holds h_int[unit g] for seqs 2tid, 2tid+1
        float wi0 = W_out[32 + g], wi1 = W_out[72 + g];
        p00 = fmaf(hint[0], wi0, p00); p01 = fmaf(hint[0], wi1, p01);
        p10 = fmaf(hint[1], wi0, p10); p11 = fmaf(hint[1], wi1, p11);
    }
    // reduce across g (lane bits 2-4)
#pragma unroll
    for (int m = 4; m <= 16; m <<= 1) {
        p00 += __shfl_xor_sync(FULL, p00, m);
        p01 += __shfl_xor_sync(FULL, p01, m);
        p10 += __shfl_xor_sync(FULL, p10, m);
        p11 += __shfl_xor_sync(FULL, p11, m);
    }
    if (g == 0) {   // lanes 0-3: tid covers seq pairs (2tid, 2tid+1)
        float4 o;
        o.x = p00 + b_out[0]; o.y = p01 + b_out[1];
        o.z = p10 + b_out[0]; o.w = p11 + b_out[1];
        ((float4*)out)[(t * B_DIM + b0) / 2 + tid] = o;
    }
}

extern "C" void kernel_launch(void* const* d_in, const int* in_sizes, int n_in,
                              void* d_out, int out_size) {
    (void)in_sizes; (void)n_in; (void)out_size;
    const float* inputs  = (const float*)d_in[0];
    const float* Wih_his = (const float*)d_in[1];
    const float* Whh_his = (const float*)d_in[2];
    const float* bih_his = (const float*)d_in[3];
    const float* bhh_his = (const float*)d_in[4];
    const float* Wih_int = (const float*)d_in[5];
    const float* Whh_int = (const float*)d_in[6];
    const float* bih_int = (const float*)d_in[7];
    const float* bhh_int = (const float*)d_in[8];
    const float* W_out   = (const float*)d_in[9];
    const float* b_out   = (const float*)d_in[10];
    float* out = (float*)d_out;

    // 4096 warps (8 seqs each), one warp per 32-thread block for
    // fine-grained register packing (higher occupancy than 4-warp blocks)
    traj_kernel<<<NWARPS, 32>>>(inputs, Wih_his, Whh_his, bih_his, bhh_his,
                                Wih_int, Whh_int, bih_int, bhh_int,
                                W_out, b_out, out);
}

// round 14
// speedup vs baseline: 10.7403x; 1.0867x over previous
#include <cuda_runtime.h>
#include <cuda_fp16.h>
#include <cstdint>

#define T_DIM 256
#define B_DIM 128
#define N_DIM 4
#define L_WIN 64
// one warp = 8 sequences (same t, 8 adjacent b); 4096 single-warp blocks
#define NWARPS 4096

// ---------- fast activations (MUFU.TANH, fp32 in/out) ----------
__device__ __forceinline__ float tanh_a(float x) {
    float y;
    asm("tanh.approx.f32 %0, %1;" : "=f"(y) : "f"(x));
    return y;
}
__device__ __forceinline__ float sig_a(float x) {
    return fmaf(0.5f, tanh_a(0.5f * x), 0.5f);
}

// ---------- fp16 pack / split helpers ----------
__device__ __forceinline__ uint32_t packh2(__half lo, __half hi) {
    __half2 v; v.x = lo; v.y = hi;
    return *reinterpret_cast<uint32_t*>(&v);
}
__device__ __forceinline__ __half2 u2h(uint32_t u) { return *reinterpret_cast<__half2*>(&u); }
__device__ __forceinline__ void splitf(float f, __half& a, __half& b) {
    a = __float2half_rn(f);
    b = __float2half_rn(f - __half2float(a));
}
__device__ __forceinline__ uint32_t wpack2(const float* W, int ld, int row, int col) {
    return packh2(__float2half_rn(W[row * ld + col]),
                  __float2half_rn(W[row * ld + col + 1]));
}

// ---------- tensor core ops ----------
__device__ __forceinline__ void mma16816(float* d, const uint32_t* a,
                                         uint32_t b0, uint32_t b1) {
    asm("mma.sync.aligned.m16n8k16.row.col.f32.f16.f16.f32 "
        "{%0,%1,%2,%3}, {%4,%5,%6,%7}, {%8,%9}, {%0,%1,%2,%3};"
        : "+f"(d[0]), "+f"(d[1]), "+f"(d[2]), "+f"(d[3])
        : "r"(a[0]), "r"(a[1]), "r"(a[2]), "r"(a[3]), "r"(b0), "r"(b1));
}
__device__ __forceinline__ uint32_t movm(uint32_t s) {
    uint32_t d;
    asm("movmatrix.sync.aligned.m8n8.trans.b16 %0, %1;" : "=r"(d) : "r"(s));
    return d;
}

// Gate-grouped ROW PERMUTATION: m-tile 2u = {i[8u..8u+7], f[8u..8u+7]},
// m-tile 2u+1 = {g[8u..8u+7], o[8u..8u+7]}. Unit-group u needs only tiles
// (2u, 2u+1), so accumulators are activated and released per group:
// 8 live fp32 accs instead of 32 -> regs under the 170 (3 warps/SMSP) cliff.
__device__ __forceinline__ int prow(int mt, int r) {
    int base = (mt & 1) ? ((r & 8) ? 96 : 64) : ((r & 8) ? 32 : 0);
    return base + 8 * (mt >> 1) + (r & 7);
}

// Fragment conventions (m16n8k16, row.col):
//   A: lane(g=l>>2, tid=l&3): a0=(r=g, c=2tid,+1) a1=(g+8, same) a2=(g, +8) a3=(g+8, +8)
//   B: b0=(k=2tid,+1; n=g)  b1=(k=2tid+8,+9; n=g)
//   C: c0,c1=(row g, col 2tid,2tid+1)  c2,c3=(row g+8, same cols)
__global__ void __launch_bounds__(32, 12) traj_kernel(
    const float* __restrict__ inputs,
    const float* __restrict__ Wih_his, const float* __restrict__ Whh_his,
    const float* __restrict__ bih_his, const float* __restrict__ bhh_his,
    const float* __restrict__ Wih_int, const float* __restrict__ Whh_int,
    const float* __restrict__ bih_int, const float* __restrict__ bhh_int,
    const float* __restrict__ W_out, const float* __restrict__ b_out,
    float* __restrict__ out)
{
    const unsigned FULL = 0xffffffffu;
    const int lane = threadIdx.x;
    const int gw = blockIdx.x;
    const int t = (T_DIM - 1) - (gw >> 4);     // long windows first
    const int b0 = (gw & 15) * 8;
    const int g = lane >> 2, tid = lane & 3;
    const __half ONE = __float2half_rn(1.0f);

    // ---- his Whh A-frags (fp16, permuted rows) ----
    uint32_t A1[8][2][4];
#pragma unroll
    for (int mt = 0; mt < 8; mt++) {
#pragma unroll
        for (int kt = 0; kt < 2; kt++) {
            int c0 = 16 * kt + 2 * tid;
            int r0 = prow(mt, g), r1 = prow(mt, g + 8);
            A1[mt][kt][0] = wpack2(Whh_his, 32, r0, c0);
            A1[mt][kt][1] = wpack2(Whh_his, 32, r1, c0);
            A1[mt][kt][2] = wpack2(Whh_his, 32, r0, c0 + 8);
            A1[mt][kt][3] = wpack2(Whh_his, 32, r1, c0 + 8);
        }
    }
    // ---- his x/bias k-tile A-frags (split-fp16 x/bias columns, permuted rows) ----
    uint32_t XA[8][2];
#pragma unroll
    for (int mt = 0; mt < 8; mt++) {
#pragma unroll
        for (int half = 0; half < 2; half++) {
            int rr = prow(mt, g + 8 * half);
            __half wx0_1, wx0_2, wx1_1, wx1_2, bb_1, bb_2;
            splitf(Wih_his[rr * 2 + 0], wx0_1, wx0_2);
            splitf(Wih_his[rr * 2 + 1], wx1_1, wx1_2);
            splitf(bih_his[rr] + bhh_his[rr], bb_1, bb_2);
            XA[mt][half] = (tid == 0) ? packh2(wx0_1, wx0_1)
                         : (tid == 1) ? packh2(wx1_1, wx1_1)
                         : (tid == 2) ? packh2(bb_1, wx0_2)
                                      : packh2(wx1_2, bb_2);
        }
    }
    // ---- int A-frags (rows already gate-grouped: [32,8] = i,f | g,o tiles) ----
    uint32_t IA1[2][2], IAX[2][2];
#pragma unroll
    for (int mt = 0; mt < 2; mt++) {
#pragma unroll
        for (int half = 0; half < 2; half++) {
            int rr = 16 * mt + g + 8 * half;
            IA1[mt][half] = wpack2(Whh_int, 8, rr, 2 * tid);
            __half wx0_1, wx0_2, wx1_1, wx1_2, bb_1, bb_2;
            splitf(Wih_int[rr * 2 + 0], wx0_1, wx0_2);
            splitf(Wih_int[rr * 2 + 1], wx1_1, wx1_2);
            splitf(bih_int[rr] + bhh_int[rr], bb_1, bb_2);
            IAX[mt][half] = (tid == 0) ? packh2(wx0_1, wx0_1)
                          : (tid == 1) ? packh2(wx1_1, wx1_1)
                          : (tid == 2) ? packh2(bb_1, wx0_2)
                                       : packh2(wx1_2, bb_2);
        }
    }

    // ---- recurrent state ----
    float cst[4][2];                 // his c: unit-group u, seq-pair slot j
#pragma unroll
    for (int u = 0; u < 4; u++) { cst[u][0] = 0.0f; cst[u][1] = 0.0f; }
    float cint[2] = {0.0f, 0.0f}, hint[2] = {0.0f, 0.0f};
    uint32_t hh[4] = {0, 0, 0, 0};   // his h fp16 pairs (unit 8u+g; seqs 2tid,2tid+1)
    uint32_t bh1[4] = {0, 0, 0, 0};  // B-frags (k=units)
    uint32_t bih1 = 0;

    int a0 = t - (L_WIN - 1);
    if (a0 < 0) a0 = 0;

    const float2* __restrict__ inp2 = (const float2*)inputs; // [T,B,N] float2
    const long STRIDE = (long)B_DIM * N_DIM;
    long base = ((long)a0 * B_DIM + (b0 + g)) * N_DIM;  // lane loads seq g's x
    float2 xh = inp2[base + 3];   // node -1 (his)
    float2 xi = inp2[base + 0];   // node 0  (int)

    for (int a = a0; a <= t; a++) {
        // prefetch next step
        float2 xhn = xh, xin = xi;
        if (a < t) { xhn = inp2[base + STRIDE + 3]; xin = inp2[base + STRIDE + 0]; }
        base += STRIDE;

        // x B-frags (k rows: x0h,x0l,x1h,x1l,1,x0h,x1h,1)
        __half x0h, x0l, x1h, x1l;
        splitf(xh.x, x0h, x0l); splitf(xh.y, x1h, x1l);
        uint32_t bx = (tid == 0) ? packh2(x0h, x0l)
                    : (tid == 1) ? packh2(x1h, x1l)
                    : (tid == 2) ? packh2(ONE, x0h)
                                 : packh2(x1h, ONE);
        splitf(xi.x, x0h, x0l); splitf(xi.y, x1h, x1l);
        uint32_t bxi = (tid == 0) ? packh2(x0h, x0l)
                     : (tid == 1) ? packh2(x1h, x1l)
                     : (tid == 2) ? packh2(ONE, x0h)
                                  : packh2(x1h, ONE);

        // --- int gates first (independent work to overlap with his chain) ---
        float di[2][4];
#pragma unroll
        for (int mt = 0; mt < 2; mt++) {
            di[mt][0] = di[mt][1] = di[mt][2] = di[mt][3] = 0.0f;
            uint32_t a1_[4] = {IA1[mt][0], IA1[mt][1], 0u, 0u};
            mma16816(di[mt], a1_, bih1, 0u);              // W @ h (k 0-7 live)
            uint32_t a2_[4] = {IAX[mt][0], IAX[mt][1], 0u, 0u};
            mma16816(di[mt], a2_, bxi, 0u);               // x + bias
        }

        // --- his: per unit-group, 6 MMAs then activate & release ---
        uint32_t nbh[4];
#pragma unroll
        for (int u = 0; u < 4; u++) {
            const int me = 2 * u, mo = 2 * u + 1;
            float de[4] = {0.0f, 0.0f, 0.0f, 0.0f};   // c0,c1=i; c2,c3=f
            float dg[4] = {0.0f, 0.0f, 0.0f, 0.0f};   // c0,c1=g; c2,c3=o
            mma16816(de, A1[me][0], bh1[0], bh1[1]);
            mma16816(de, A1[me][1], bh1[2], bh1[3]);
            uint32_t xae[4] = {XA[me][0], XA[me][1], 0u, 0u};
            mma16816(de, xae, bx, 0u);
            mma16816(dg, A1[mo][0], bh1[0], bh1[1]);
            mma16816(dg, A1[mo][1], bh1[2], bh1[3]);
            uint32_t xao[4] = {XA[mo][0], XA[mo][1], 0u, 0u};
            mma16816(dg, xao, bx, 0u);

            __half hp[2];
#pragma unroll
            for (int j = 0; j < 2; j++) {
                float si = sig_a(de[j]);
                float sf = sig_a(de[2 + j]);
                float tg = tanh_a(dg[j]);
                float so = sig_a(dg[2 + j]);
                float c = fmaf(sf, cst[u][j], si * tg);
                cst[u][j] = c;
                hp[j] = __float2half_rn(so * tanh_a(c));
            }
            hh[u] = packh2(hp[0], hp[1]);
            nbh[u] = movm(hh[u]);
        }

        // --- int activations ---
#pragma unroll
        for (int j = 0; j < 2; j++) {
            float si = sig_a(di[0][j]);
            float sf = sig_a(di[0][2 + j]);
            float tg = tanh_a(di[1][j]);
            float so = sig_a(di[1][2 + j]);
            float c = fmaf(sf, cint[j], si * tg);
            cint[j] = c;
            hint[j] = so * tanh_a(c);
        }
        bih1 = movm(packh2(__float2half_rn(hint[0]), __float2half_rn(hint[1])));

        bh1[0] = nbh[0]; bh1[1] = nbh[1]; bh1[2] = nbh[2]; bh1[3] = nbh[3];
        xh = xhn; xi = xin;
    }

    // ---- output head (his h from fp16 pairs; int h fp32) ----
    float p00 = 0.0f, p01 = 0.0f, p10 = 0.0f, p11 = 0.0f;
#pragma unroll
    for (int u = 0; u < 4; u++) {
        int unit = 8 * u + g;
        float2 hf = __half22float2(u2h(hh[u]));   // x: seq 2tid, y: seq 2tid+1
        float wo0 = W_out[unit], wo1 = W_out[40 + unit];
        p00 = fmaf(hf.x, wo0, p00); p01 = fmaf(hf.x, wo1, p01);
        p10 = fmaf(hf.y, wo0, p10); p11 = fmaf(hf.y, wo1, p11);
    }
    {   // int part: lane holds h_int[unit g] for seqs 2tid, 2tid+1
        float wi0 = W_out[32 + g], wi1 = W_out[72 + g];
        p00 = fmaf(hint[0], wi0, p00); p01 = fmaf(hint[0], wi1, p01);
        p10 = fmaf(hint[1], wi0, p10); p11 = fmaf(hint[1], wi1, p11);
    }
    // reduce across g (lane bits 2-4)
#pragma unroll
    for (int m = 4; m <= 16; m <<= 1) {
        p00 += __shfl_xor_sync(FULL, p00, m);
        p01 += __shfl_xor_sync(FULL, p01, m);
        p10 += __shfl_xor_sync(FULL, p10, m);
        p11 += __shfl_xor_sync(FULL, p11, m);
    }
    if (g == 0) {   // lanes 0-3: tid covers seq pairs (2tid, 2tid+1)
        float4 o;
        o.x = p00 + b_out[0]; o.y = p01 + b_out[1];
        o.z = p10 + b_out[0]; o.w = p11 + b_out[1];
        ((float4*)out)[(t * B_DIM + b0) / 2 + tid] = o;
    }
}

extern "C" void kernel_launch(void* const* d_in, const int* in_sizes, int n_in,
                              void* d_out, int out_size) {
    (void)in_sizes; (void)n_in; (void)out_size;
    const float* inputs  = (const float*)d_in[0];
    const float* Wih_his = (const float*)d_in[1];
    const float* Whh_his = (const float*)d_in[2];
    const float* bih_his = (const float*)d_in[3];
    const float* bhh_his = (const float*)d_in[4];
    const float* Wih_int = (const float*)d_in[5];
    const float* Whh_int = (const float*)d_in[6];
    const float* bih_int = (const float*)d_in[7];
    const float* bhh_int = (const float*)d_in[8];
    const float* W_out   = (const float*)d_in[9];
    const float* b_out   = (const float*)d_in[10];
    float* out = (float*)d_out;

    // 4096 warps (8 seqs each), one warp per 32-thread block
    traj_kernel<<<NWARPS, 32>>>(inputs, Wih_his, Whh_his, bih_his, bhh_his,
                                Wih_int, Whh_int, bih_int, bhh_int,
                                W_out, b_out, out);
}

// round 15
// speedup vs baseline: 11.0513x; 1.0290x over previous
#include <cuda_runtime.h>
#include <cuda_fp16.h>
#include <cstdint>

#define T_DIM 256
#define B_DIM 128
#define N_DIM 4
#define L_WIN 64
// one warp = 8 sequences (same t, 8 adjacent b); 4096 single-warp blocks
#define NWARPS 4096

// ---------- fast activations ----------
__device__ __forceinline__ float tanh_a(float x) {
    float y;
    asm("tanh.approx.f32 %0, %1;" : "=f"(y) : "f"(x));
    return y;
}
// sigmoid with the 0.5 input scale FOLDED INTO THE WEIGHTS:
// accumulator already holds 0.5*x, so sigma = 0.5*tanh(acc) + 0.5
__device__ __forceinline__ float sig_pre(float y) {
    return fmaf(0.5f, tanh_a(y), 0.5f);
}
__device__ __forceinline__ uint32_t tanh2u(uint32_t x) {
    uint32_t y;
    asm("tanh.approx.f16x2 %0, %1;" : "=r"(y) : "r"(x));
    return y;
}
// pack two fp32 into f16x2: lo <- second operand
__device__ __forceinline__ uint32_t cvt2(float hi, float lo) {
    uint32_t r;
    asm("cvt.rn.f16x2.f32 %0, %1, %2;" : "=r"(r) : "f"(hi), "f"(lo));
    return r;
}

// ---------- fp16 pack / split helpers ----------
__device__ __forceinline__ uint32_t packh2(__half lo, __half hi) {
    __half2 v; v.x = lo; v.y = hi;
    return *reinterpret_cast<uint32_t*>(&v);
}
__device__ __forceinline__ __half2 u2h(uint32_t u) { return *reinterpret_cast<__half2*>(&u); }
__device__ __forceinline__ uint32_t h2u(__half2 h) { return *reinterpret_cast<uint32_t*>(&h); }
__device__ __forceinline__ void splitf(float f, __half& a, __half& b) {
    a = __float2half_rn(f);
    b = __float2half_rn(f - __half2float(a));
}
// fp16 weight pair with fold-in scale (0.5 for sigmoid rows, 1.0 for tanh rows)
__device__ __forceinline__ uint32_t wpack2s(const float* W, int ld, int row, int col, float s) {
    return packh2(__float2half_rn(s * W[row * ld + col]),
                  __float2half_rn(s * W[row * ld + col + 1]));
}

// ---------- tensor core ops ----------
__device__ __forceinline__ void mma16816(float* d, const uint32_t* a,
                                         uint32_t b0, uint32_t b1) {
    asm("mma.sync.aligned.m16n8k16.row.col.f32.f16.f16.f32 "
        "{%0,%1,%2,%3}, {%4,%5,%6,%7}, {%8,%9}, {%0,%1,%2,%3};"
        : "+f"(d[0]), "+f"(d[1]), "+f"(d[2]), "+f"(d[3])
        : "r"(a[0]), "r"(a[1]), "r"(a[2]), "r"(a[3]), "r"(b0), "r"(b1));
}
__device__ __forceinline__ uint32_t movm(uint32_t s) {
    uint32_t d;
    asm("movmatrix.sync.aligned.m8n8.trans.b16 %0, %1;" : "=r"(d) : "r"(s));
    return d;
}

// Gate-grouped ROW PERMUTATION: m-tile 2u = {i[8u..], f[8u..]},
// m-tile 2u+1 = {g[8u..], o[8u..]}; unit-group u uses tiles (2u, 2u+1) only,
// so 8 live fp32 accumulators, activated and released per group.
__device__ __forceinline__ int prow(int mt, int r) {
    int base = (mt & 1) ? ((r & 8) ? 96 : 64) : ((r & 8) ? 32 : 0);
    return base + 8 * (mt >> 1) + (r & 7);
}
// weight fold-scale for permuted row: sigmoid rows (i,f,o) 0.5; tanh rows (g) 1.0
__device__ __forceinline__ float pscale(int mt, int r) {
    return ((mt & 1) && !(r & 8)) ? 1.0f : 0.5f;   // odd tile, low rows = g-gate
}

__global__ void __launch_bounds__(32, 12) traj_kernel(
    const float* __restrict__ inputs,
    const float* __restrict__ Wih_his, const float* __restrict__ Whh_his,
    const float* __restrict__ bih_his, const float* __restrict__ bhh_his,
    const float* __restrict__ Wih_int, const float* __restrict__ Whh_int,
    const float* __restrict__ bih_int, const float* __restrict__ bhh_int,
    const float* __restrict__ W_out, const float* __restrict__ b_out,
    float* __restrict__ out)
{
    const unsigned FULL = 0xffffffffu;
    const int lane = threadIdx.x;
    const int gw = blockIdx.x;
    const int t = (T_DIM - 1) - (gw >> 4);     // long windows first
    const int b0 = (gw & 15) * 8;
    const int g = lane >> 2, tid = lane & 3;
    const __half ONE = __float2half_rn(1.0f);
    const __half2 H05 = __half2half2(__float2half_rn(0.5f));

    // ---- his Whh A-frags (fp16, permuted rows, sigmoid-scale folded) ----
    uint32_t A1[8][2][4];
#pragma unroll
    for (int mt = 0; mt < 8; mt++) {
#pragma unroll
        for (int kt = 0; kt < 2; kt++) {
            int c0 = 16 * kt + 2 * tid;
            int r0 = prow(mt, g), r1 = prow(mt, g + 8);
            float s0 = pscale(mt, g), s1 = pscale(mt, g + 8);
            A1[mt][kt][0] = wpack2s(Whh_his, 32, r0, c0, s0);
            A1[mt][kt][1] = wpack2s(Whh_his, 32, r1, c0, s1);
            A1[mt][kt][2] = wpack2s(Whh_his, 32, r0, c0 + 8, s0);
            A1[mt][kt][3] = wpack2s(Whh_his, 32, r1, c0 + 8, s1);
        }
    }
    // ---- his x/bias k-tile A-frags (split-fp16, permuted rows, scaled) ----
    uint32_t XA[8][2];
#pragma unroll
    for (int mt = 0; mt < 8; mt++) {
#pragma unroll
        for (int half = 0; half < 2; half++) {
            int rr = prow(mt, g + 8 * half);
            float s = pscale(mt, g + 8 * half);
            __half wx0_1, wx0_2, wx1_1, wx1_2, bb_1, bb_2;
            splitf(s * Wih_his[rr * 2 + 0], wx0_1, wx0_2);
            splitf(s * Wih_his[rr * 2 + 1], wx1_1, wx1_2);
            splitf(s * (bih_his[rr] + bhh_his[rr]), bb_1, bb_2);
            XA[mt][half] = (tid == 0) ? packh2(wx0_1, wx0_1)
                         : (tid == 1) ? packh2(wx1_1, wx1_1)
                         : (tid == 2) ? packh2(bb_1, wx0_2)
                                      : packh2(wx1_2, bb_2);
        }
    }
    // ---- int A-frags (rows naturally gate-grouped: tile0 = i,f; tile1 = g,o) ----
    uint32_t IA1[2][2], IAX[2][2];
#pragma unroll
    for (int mt = 0; mt < 2; mt++) {
#pragma unroll
        for (int half = 0; half < 2; half++) {
            int rr = 16 * mt + g + 8 * half;
            float s = (mt == 1 && half == 0) ? 1.0f : 0.5f;  // g rows unscaled
            IA1[mt][half] = wpack2s(Whh_int, 8, rr, 2 * tid, s);
            __half wx0_1, wx0_2, wx1_1, wx1_2, bb_1, bb_2;
            splitf(s * Wih_int[rr * 2 + 0], wx0_1, wx0_2);
            splitf(s * Wih_int[rr * 2 + 1], wx1_1, wx1_2);
            splitf(s * (bih_int[rr] + bhh_int[rr]), bb_1, bb_2);
            IAX[mt][half] = (tid == 0) ? packh2(wx0_1, wx0_1)
                          : (tid == 1) ? packh2(wx1_1, wx1_1)
                          : (tid == 2) ? packh2(bb_1, wx0_2)
                                       : packh2(wx1_2, bb_2);
        }
    }

    // ---- recurrent state ----
    float cst[4][2];                 // his c: unit-group u, seq-pair slot j
#pragma unroll
    for (int u = 0; u < 4; u++) { cst[u][0] = 0.0f; cst[u][1] = 0.0f; }
    float cint0 = 0.0f, cint1 = 0.0f;
    uint32_t hh[4] = {0, 0, 0, 0};   // his h half2 (unit 8u+g; seqs 2tid,2tid+1)
    uint32_t hintp = 0;              // int h half2
    uint32_t bh1[4] = {0, 0, 0, 0};  // B-frags (k=units)
    uint32_t bih1 = 0;

    int a0 = t - (L_WIN - 1);
    if (a0 < 0) a0 = 0;

    const float2* __restrict__ inp2 = (const float2*)inputs; // [T,B,N] float2
    const long STRIDE = (long)B_DIM * N_DIM;
    long base = ((long)a0 * B_DIM + (b0 + g)) * N_DIM;  // lane loads seq g's x
    float2 xh = inp2[base + 3];   // node -1 (his)
    float2 xi = inp2[base + 0];   // node 0  (int)

    for (int a = a0; a <= t; a++) {
        // prefetch next step
        float2 xhn = xh, xin = xi;
        if (a < t) { xhn = inp2[base + STRIDE + 3]; xin = inp2[base + STRIDE + 0]; }
        base += STRIDE;

        // x B-frags (k rows: x0h,x0l,x1h,x1l,1,x0h,x1h,1)
        __half x0h, x0l, x1h, x1l;
        splitf(xh.x, x0h, x0l); splitf(xh.y, x1h, x1l);
        uint32_t bx = (tid == 0) ? packh2(x0h, x0l)
                    : (tid == 1) ? packh2(x1h, x1l)
                    : (tid == 2) ? packh2(ONE, x0h)
                                 : packh2(x1h, ONE);
        splitf(xi.x, x0h, x0l); splitf(xi.y, x1h, x1l);
        uint32_t bxi = (tid == 0) ? packh2(x0h, x0l)
                     : (tid == 1) ? packh2(x1h, x1l)
                     : (tid == 2) ? packh2(ONE, x0h)
                                  : packh2(x1h, ONE);

        // --- int gates first (independent work to overlap with his chain) ---
        float di[2][4];
#pragma unroll
        for (int mt = 0; mt < 2; mt++) {
            di[mt][0] = di[mt][1] = di[mt][2] = di[mt][3] = 0.0f;
            uint32_t a1_[4] = {IA1[mt][0], IA1[mt][1], 0u, 0u};
            mma16816(di[mt], a1_, bih1, 0u);              // W @ h (k 0-7 live)
            uint32_t a2_[4] = {IAX[mt][0], IAX[mt][1], 0u, 0u};
            mma16816(di[mt], a2_, bxi, 0u);               // x + bias
        }

        // --- his: per unit-group, 6 MMAs then activate & release ---
        uint32_t nbh[4];
#pragma unroll
        for (int u = 0; u < 4; u++) {
            const int me = 2 * u, mo = 2 * u + 1;
            float de[4] = {0.0f, 0.0f, 0.0f, 0.0f};   // c0,c1 = i; c2,c3 = f (pre-scaled 0.5)
            float dg[4] = {0.0f, 0.0f, 0.0f, 0.0f};   // c0,c1 = g; c2,c3 = o (o pre-scaled)
            mma16816(de, A1[me][0], bh1[0], bh1[1]);
            mma16816(de, A1[me][1], bh1[2], bh1[3]);
            uint32_t xae[4] = {XA[me][0], XA[me][1], 0u, 0u};
            mma16816(de, xae, bx, 0u);
            mma16816(dg, A1[mo][0], bh1[0], bh1[1]);
            mma16816(dg, A1[mo][1], bh1[2], bh1[3]);
            uint32_t xao[4] = {XA[mo][0], XA[mo][1], 0u, 0u};
            mma16816(dg, xao, bx, 0u);

            // c-path activations in fp32 (error-sensitive)
            float si0 = sig_pre(de[0]), sf0 = sig_pre(de[2]), tg0 = tanh_a(dg[0]);
            float si1 = sig_pre(de[1]), sf1 = sig_pre(de[3]), tg1 = tanh_a(dg[1]);
            float c0 = fmaf(sf0, cst[u][0], si0 * tg0); cst[u][0] = c0;
            float c1 = fmaf(sf1, cst[u][1], si1 * tg1); cst[u][1] = c1;
            // h-path in f16x2 (h is fp16 anyway): sigma(o) pair + tanh(c) pair
            uint32_t po = cvt2(dg[3], dg[2]);     // lo=j0, hi=j1 (pre-scaled 0.5)
            uint32_t pc = cvt2(c1, c0);
            __half2 so2 = __hfma2(u2h(tanh2u(po)), H05, H05);
            __half2 th2 = u2h(tanh2u(pc));
            hh[u] = h2u(__hmul2(so2, th2));       // = packh2(h_j0, h_j1)
            nbh[u] = movm(hh[u]);
        }

        // --- int activations (same split) ---
        {
            float si0 = sig_pre(di[0][0]), sf0 = sig_pre(di[0][2]), tg0 = tanh_a(di[1][0]);
            float si1 = sig_pre(di[0][1]), sf1 = sig_pre(di[0][3]), tg1 = tanh_a(di[1][1]);
            cint0 = fmaf(sf0, cint0, si0 * tg0);
            cint1 = fmaf(sf1, cint1, si1 * tg1);
            uint32_t po = cvt2(di[1][3], di[1][2]);
            uint32_t pc = cvt2(cint1, cint0);
            __half2 so2 = __hfma2(u2h(tanh2u(po)), H05, H05);
            __half2 th2 = u2h(tanh2u(pc));
            hintp = h2u(__hmul2(so2, th2));
            bih1 = movm(hintp);
        }

        bh1[0] = nbh[0]; bh1[1] = nbh[1]; bh1[2] = nbh[2]; bh1[3] = nbh[3];
        xh = xhn; xi = xin;
    }

    // ---- output head (h from half2 pairs) ----
    float p00 = 0.0f, p01 = 0.0f, p10 = 0.0f, p11 = 0.0f;
#pragma unroll
    for (int u = 0; u < 4; u++) {
        int unit = 8 * u + g;
        float2 hf = __half22float2(u2h(hh[u]));   // x: seq 2tid, y: seq 2tid+1
        float wo0 = W_out[unit], wo1 = W_out[40 + unit];
        p00 = fmaf(hf.x, wo0, p00); p01 = fmaf(hf.x, wo1, p01);
        p10 = fmaf(hf.y, wo0, p10); p11 = fmaf(hf.y, wo1, p11);
    }
    {   // int part: lane holds h_int[unit g] for seqs 2tid, 2tid+1
        float2 hf = __half22float2(u2h(hintp));
        float wi0 = W_out[32 + g], wi1 = W_out[72 + g];
        p00 = fmaf(hf.x, wi0, p00); p01 = fmaf(hf.x, wi1, p01);
        p10 = fmaf(hf.y, wi0, p10); p11 = fmaf(hf.y, wi1, p11);
    }
    // reduce across g (lane bits 2-4)
#pragma unroll
    for (int m = 4; m <= 16; m <<= 1) {
        p00 += __shfl_xor_sync(FULL, p00, m);
        p01 += __shfl_xor_sync(FULL, p01, m);
        p10 += __shfl_xor_sync(FULL, p10, m);
        p11 += __shfl_xor_sync(FULL, p11, m);
    }
    if (g == 0) {   // lanes 0-3: tid covers seq pairs (2tid, 2tid+1)
        float4 o;
        o.x = p00 + b_out[0]; o.y = p01 + b_out[1];
        o.z = p10 + b_out[0]; o.w = p11 + b_out[1];
        ((float4*)out)[(t * B_DIM + b0) / 2 + tid] = o;
    }
}

extern "C" void kernel_launch(void* const* d_in, const int* in_sizes, int n_in,
                              void* d_out, int out_size) {
    (void)in_sizes; (void)n_in; (void)out_size;
    const float* inputs  = (const float*)d_in[0];
    const float* Wih_his = (const float*)d_in[1];
    const float* Whh_his = (const float*)d_in[2];
    const float* bih_his = (const float*)d_in[3];
    const float* bhh_his = (const float*)d_in[4];
    const float* Wih_int = (const float*)d_in[5];
    const float* Whh_int = (const float*)d_in[6];
    const float* bih_int = (const float*)d_in[7];
    const float* bhh_int = (const float*)d_in[8];
    const float* W_out   = (const float*)d_in[9];
    const float* b_out   = (const float*)d_in[10];
    float* out = (float*)d_out;

    // 4096 warps (8 seqs each), one warp per 32-thread block
    traj_kernel<<<NWARPS, 32>>>(inputs, Wih_his, Whh_his, bih_his, bhh_his,
                                Wih_int, Whh_int, bih_int, bhh_int,
                                W_out, b_out, out);
}